// round 14
// baseline (speedup 1.0000x reference)
#include <cuda_runtime.h>
#include <cuda_fp16.h>
#include <math.h>
#include <stdint.h>

// Problem constants (fixed by the dataset)
#define CN   100000
#define CE   1600000
#define CH   128
#define CM   150000
#define CKC  60000
#define CB   64
#define CCOUT 10

// ---------------- scratch (device globals; no allocation) ----------------
__device__ __align__(128) __half g_xwh [(size_t)CN * CH];    // fp16 x @ W_in
__device__ __align__(128) __half g_hh  [(size_t)CN * CH];    // fp16 relu(gcn1)
__device__ __align__(128) __half g_znh [(size_t)CN * CH];    // fp16 zn
__device__ __align__(128) __half g_yeh [(size_t)CN * CH];    // fp16 ye
__device__ __align__(128) __half g_xph [(size_t)CKC * 2 * CH]; // fp16 [add|max] cover pool
__device__ __align__(128) __half g_xwsh[(size_t)CKC * CH];   // fp16 dinvp*(xp@W_blk)
__device__ __align__(128) float g_hp  [(size_t)CKC * CH];
__device__ __align__(128) float g_deg  [CN];
__device__ __align__(128) float g_dinv [CN];
__device__ __align__(128) float g_ye1  [CN];
__device__ __align__(128) float g_dinvp[CKC];
__device__ __align__(128) float g_Sh [CB * CH];
__device__ __align__(128) float g_Xh [CB * CH];
__device__ __align__(128) float g_Shp[CB * CH];
__device__ __align__(128) float g_Xhp[CB * CH];
__device__ __align__(128) float g_cc [CB];

// CSR-E: dst -> (src, w)
__device__ __align__(128) int  g_cntE[CN];
__device__ __align__(128) int  g_offE[CN + 1];
__device__ __align__(128) int  g_curE[CN];
__device__ __align__(128) int2 g_edges[CE];
// CSR-C: cluster -> cover_node entries
__device__ __align__(128) int  g_cntC[CKC];
__device__ __align__(128) int  g_offC[CKC + 1];
__device__ __align__(128) int  g_curC[CKC];
__device__ __align__(128) int  g_cnC [CM];
// CSR-N: node -> cover_cluster entries
__device__ __align__(128) int  g_cntN[CN];
__device__ __align__(128) int  g_offN[CN + 1];
__device__ __align__(128) int  g_curN[CN];
__device__ __align__(128) int  g_ccN [CM];

// scan temporaries (bases: E=0, C=64, N=128; each needs <64 blocks)
__device__ int g_blockSums[256];
__device__ int g_blockOffs[256];

#define SCAN_BS 2048

// ---------------- process-lifetime streams/events ----------------
static cudaStream_t hs1, hs2;
static cudaEvent_t hevStart, hevGemm1, hevFillE, hevFillCN, hevH,
                   hevDinvp, hevZeroP, hevSide;
namespace {
struct StreamInit {
    StreamInit() {
        cudaStreamCreateWithFlags(&hs1, cudaStreamNonBlocking);
        cudaStreamCreateWithFlags(&hs2, cudaStreamNonBlocking);
        cudaEventCreateWithFlags(&hevStart,  cudaEventDisableTiming);
        cudaEventCreateWithFlags(&hevGemm1,  cudaEventDisableTiming);
        cudaEventCreateWithFlags(&hevFillE,  cudaEventDisableTiming);
        cudaEventCreateWithFlags(&hevFillCN, cudaEventDisableTiming);
        cudaEventCreateWithFlags(&hevH,      cudaEventDisableTiming);
        cudaEventCreateWithFlags(&hevDinvp,  cudaEventDisableTiming);
        cudaEventCreateWithFlags(&hevZeroP,  cudaEventDisableTiming);
        cudaEventCreateWithFlags(&hevSide,   cudaEventDisableTiming);
    }
};
static StreamInit s_init_;
}

// ---------------- histograms ----------------
__global__ void k_histE(const int* __restrict__ dst, int E) {
    int i = blockIdx.x * blockDim.x + threadIdx.x;
    if (i < E) atomicAdd(&g_cntE[dst[i]], 1);
}
__global__ void k_histM(const int* __restrict__ cc, const int* __restrict__ cn, int M) {
    int i = blockIdx.x * blockDim.x + threadIdx.x;
    if (i < M) {
        atomicAdd(&g_cntC[cc[i]], 1);
        atomicAdd(&g_cntN[cn[i]], 1);
    }
}

// ---------------- generic 3-phase scan ----------------
__global__ __launch_bounds__(256)
void k_scanA1(const int* __restrict__ cnt, int n, int base) {
    int t = threadIdx.x;
    int off0 = blockIdx.x * SCAN_BS + t * 8;
    int s = 0;
    #pragma unroll
    for (int k = 0; k < 8; k++) {
        int idx = off0 + k;
        if (idx < n) s += cnt[idx];
    }
    __shared__ int red[256];
    red[t] = s;
    __syncthreads();
    #pragma unroll
    for (int d = 128; d > 0; d >>= 1) {
        if (t < d) red[t] += red[t + d];
        __syncthreads();
    }
    if (t == 0) g_blockSums[base + blockIdx.x] = red[0];
}

__global__ void k_scanB1(int nb, int base, int* __restrict__ totalOut) {
    if (threadIdx.x == 0) {
        int run = 0;
        for (int i = 0; i < nb; i++) {
            int v = g_blockSums[base + i];
            g_blockOffs[base + i] = run;
            run += v;
        }
        *totalOut = run;
    }
}

__global__ __launch_bounds__(256)
void k_scanC1(const int* __restrict__ cnt, int* __restrict__ off, int* __restrict__ cur,
              int n, int base) {
    int t = threadIdx.x;
    int off0 = blockIdx.x * SCAN_BS + t * 8;
    int v[8];
    int s = 0;
    #pragma unroll
    for (int k = 0; k < 8; k++) {
        int idx = off0 + k;
        v[k] = (idx < n) ? cnt[idx] : 0;
        s += v[k];
    }
    __shared__ int red[256];
    red[t] = s;
    __syncthreads();
    #pragma unroll
    for (int d = 1; d < 256; d <<= 1) {
        int x = (t >= d) ? red[t - d] : 0;
        __syncthreads();
        red[t] += x;
        __syncthreads();
    }
    int pre = g_blockOffs[base + blockIdx.x] + red[t] - s;
    #pragma unroll
    for (int k = 0; k < 8; k++) {
        int idx = off0 + k;
        if (idx < n) { off[idx] = pre; cur[idx] = pre; }
        pre += v[k];
    }
}

// ---------------- CSR fills ----------------
__global__ void k_fillE(const int* __restrict__ src, const int* __restrict__ dst,
                        const float* __restrict__ w, int E) {
    int i = blockIdx.x * blockDim.x + threadIdx.x;
    if (i >= E) return;
    int d = dst[i];
    float wv = w[i];
    int pos = atomicAdd(&g_curE[d], 1);
    g_edges[pos] = make_int2(src[i], __float_as_int(wv));
    atomicAdd(&g_deg[d], wv);
}
__global__ void k_fillCN(const int* __restrict__ cn, const int* __restrict__ cc, int M) {
    int i = blockIdx.x * blockDim.x + threadIdx.x;
    if (i >= M) return;
    int node = cn[i], cl = cc[i];
    int pc = atomicAdd(&g_curC[cl], 1);
    g_cnC[pc] = node;
    int pn = atomicAdd(&g_curN[node], 1);
    g_ccN[pn] = cl;
}

__global__ void k_dinv(int N) {
    int i = blockIdx.x * blockDim.x + threadIdx.x;
    if (i < N) g_dinv[i] = rsqrtf(g_deg[i] + 1.0f);
}

// ---------------- fp16 helpers ----------------
__device__ __forceinline__ void fma_half_row(float4& acc, float c, uint2 u) {
    float2 f0 = __half22float2(*(__half2*)&u.x);
    float2 f1 = __half22float2(*(__half2*)&u.y);
    acc.x = fmaf(c, f0.x, acc.x); acc.y = fmaf(c, f0.y, acc.y);
    acc.z = fmaf(c, f1.x, acc.z); acc.w = fmaf(c, f1.y, acc.w);
}
__device__ __forceinline__ uint2 pack_half4(float4 v) {
    __half2 h0 = __floats2half2_rn(v.x, v.y);
    __half2 h1 = __floats2half2_rn(v.z, v.w);
    uint2 u;
    u.x = *(uint32_t*)&h0;
    u.y = *(uint32_t*)&h1;
    return u;
}

// ---------------- GCN pass 1 gather (lane-coop edges, fp16 rows) ----------------
__global__ void gather_gcn1(const float* __restrict__ b_in, int N) {
    int wid = (blockIdx.x * blockDim.x + threadIdx.x) >> 5;
    if (wid >= N) return;
    int lane = threadIdx.x & 31;
    int beg = __ldg(&g_offE[wid]), end = __ldg(&g_offE[wid + 1]);
    float dn = __ldg(&g_dinv[wid]);
    float4 acc = make_float4(0.f, 0.f, 0.f, 0.f);
    int e = beg;
    // lane-cooperative 8-edge batches: lanes 0..7 load edges + compute coeff
    for (; e + 8 <= end; e += 8) {
        int mysrc = 0; float myc = 0.f;
        if (lane < 8) {
            int2 ed = __ldg(&g_edges[e + lane]);
            mysrc = ed.x;
            myc = __int_as_float(ed.y) * dn * __ldg(&g_dinv[ed.x]);
        }
        #pragma unroll
        for (int q = 0; q < 8; q++) {
            int srcq = __shfl_sync(0xffffffffu, mysrc, q);
            float cq = __shfl_sync(0xffffffffu, myc, q);
            uint2 u = __ldg((const uint2*)(g_xwh + (size_t)srcq * CH) + lane);
            fma_half_row(acc, cq, u);
        }
    }
    // scalar tail (<=7 edges, broadcast loads)
    for (; e < end; e++) {
        int2 e0 = __ldg(&g_edges[e]);
        float c0 = __int_as_float(e0.y) * dn * __ldg(&g_dinv[e0.x]);
        uint2 u0 = __ldg((const uint2*)(g_xwh + (size_t)e0.x * CH) + lane);
        fma_half_row(acc, c0, u0);
    }
    // self term + bias + relu
    uint2 us = __ldg((const uint2*)(g_xwh + (size_t)wid * CH) + lane);
    float2 s0 = __half22float2(*(__half2*)&us.x);
    float2 s1 = __half22float2(*(__half2*)&us.y);
    float4 bv = __ldg((const float4*)b_in + lane);
    float dd = dn * dn;
    acc.x = fmaxf(fmaf(dd, s0.x, acc.x) + bv.x, 0.f);
    acc.y = fmaxf(fmaf(dd, s0.y, acc.y) + bv.y, 0.f);
    acc.z = fmaxf(fmaf(dd, s1.x, acc.z) + bv.z, 0.f);
    acc.w = fmaxf(fmaf(dd, s1.y, acc.w) + bv.w, 0.f);
    *((uint2*)(g_hh + (size_t)wid * CH) + lane) = pack_half4(acc);
}

// ---------------- GCN pass 2 gather (lane-coop edges, fp16, covered-only) ----------------
__global__ void gather_ye(int N) {
    int wid = (blockIdx.x * blockDim.x + threadIdx.x) >> 5;
    if (wid >= N) return;
    if (__ldg(&g_offN[wid]) == __ldg(&g_offN[wid + 1])) return;
    int lane = threadIdx.x & 31;
    int beg = __ldg(&g_offE[wid]), end = __ldg(&g_offE[wid + 1]);
    float4 acc = make_float4(0.f, 0.f, 0.f, 0.f);
    int e = beg;
    for (; e + 8 <= end; e += 8) {
        int mysrc = 0; float myw = 0.f;
        if (lane < 8) {
            int2 ed = __ldg(&g_edges[e + lane]);
            mysrc = ed.x;
            myw = __int_as_float(ed.y);
        }
        #pragma unroll
        for (int q = 0; q < 8; q++) {
            int srcq = __shfl_sync(0xffffffffu, mysrc, q);
            float wq = __shfl_sync(0xffffffffu, myw, q);
            uint2 u = __ldg((const uint2*)(g_znh + (size_t)srcq * CH) + lane);
            fma_half_row(acc, wq, u);
        }
    }
    for (; e < end; e++) {
        int2 e0 = __ldg(&g_edges[e]);
        uint2 u0 = __ldg((const uint2*)(g_znh + (size_t)e0.x * CH) + lane);
        fma_half_row(acc, __int_as_float(e0.y), u0);
    }
    *((uint2*)(g_yeh + (size_t)wid * CH) + lane) = pack_half4(acc);
}

// ---------------- cover pooling gather (fp16 h in, fp16 xp out) ----------------
__global__ void gather_xp(int KC) {
    int wid = (blockIdx.x * blockDim.x + threadIdx.x) >> 5;
    if (wid >= KC) return;
    int lane = threadIdx.x & 31;
    int beg = __ldg(&g_offC[wid]), end = __ldg(&g_offC[wid + 1]);
    float4 add = make_float4(0.f, 0.f, 0.f, 0.f);
    float4 mx  = make_float4(0.f, 0.f, 0.f, 0.f);
    for (int j = beg; j < end; j++) {
        int node = __ldg(&g_cnC[j]);
        uint2 u = __ldg((const uint2*)(g_hh + (size_t)node * CH) + lane);
        float2 f0 = __half22float2(*(__half2*)&u.x);
        float2 f1 = __half22float2(*(__half2*)&u.y);
        add.x += f0.x; add.y += f0.y; add.z += f1.x; add.w += f1.y;
        mx.x = fmaxf(mx.x, f0.x); mx.y = fmaxf(mx.y, f0.y);
        mx.z = fmaxf(mx.z, f1.x); mx.w = fmaxf(mx.w, f1.y);
    }
    __half* xp = g_xph + (size_t)wid * (2 * CH);
    *((uint2*)xp + lane) = pack_half4(add);
    *((uint2*)(xp + CH) + lane) = pack_half4(mx);
}

// ---------------- zn = C xws gather (fp16 xws in), store fp16 ----------------
__global__ void gather_zn(int N) {
    int wid = (blockIdx.x * blockDim.x + threadIdx.x) >> 5;
    if (wid >= N) return;
    int lane = threadIdx.x & 31;
    int beg = __ldg(&g_offN[wid]), end = __ldg(&g_offN[wid + 1]);
    float4 acc = make_float4(0.f, 0.f, 0.f, 0.f);
    for (int j = beg; j < end; j++) {
        int cl = __ldg(&g_ccN[j]);
        uint2 u = __ldg((const uint2*)(g_xwsh + (size_t)cl * CH) + lane);
        fma_half_row(acc, 1.0f, u);
    }
    *((uint2*)(g_znh + (size_t)wid * CH) + lane) = pack_half4(acc);
}

// ---------------- hp gather (fp16 ye + fp16 xws in) ----------------
__global__ void gather_hp(const float* __restrict__ b_blk, int KC) {
    int wid = (blockIdx.x * blockDim.x + threadIdx.x) >> 5;
    if (wid >= KC) return;
    int lane = threadIdx.x & 31;
    int beg = __ldg(&g_offC[wid]), end = __ldg(&g_offC[wid + 1]);
    float4 acc = make_float4(0.f, 0.f, 0.f, 0.f);
    for (int j = beg; j < end; j++) {
        int node = __ldg(&g_cnC[j]);
        uint2 u = __ldg((const uint2*)(g_yeh + (size_t)node * CH) + lane);
        fma_half_row(acc, 1.0f, u);
    }
    float dp = __ldg(&g_dinvp[wid]);
    uint2 ux = __ldg((const uint2*)(g_xwsh + (size_t)wid * CH) + lane);
    float2 x0 = __half22float2(*(__half2*)&ux.x);
    float2 x1 = __half22float2(*(__half2*)&ux.y);
    float4 bv = __ldg((const float4*)b_blk + lane);
    acc.x = fmaxf(fmaf(dp, acc.x + x0.x, bv.x), 0.f);
    acc.y = fmaxf(fmaf(dp, acc.y + x0.y, bv.y), 0.f);
    acc.z = fmaxf(fmaf(dp, acc.z + x1.x, bv.z), 0.f);
    acc.w = fmaxf(fmaf(dp, acc.w + x1.y, bv.w), 0.f);
    *((float4*)(g_hp + (size_t)wid * CH) + lane) = acc;
}

// ---------------- aprime(ones) scalar chain ----------------
__global__ void k_ye1g(int N) {
    int n = blockIdx.x * blockDim.x + threadIdx.x;
    if (n >= N) return;
    int beg = g_offE[n], end = g_offE[n + 1];
    float s = 0.f;
    for (int e = beg; e < end; e++) {
        int2 ed = __ldg(&g_edges[e]);
        s += __int_as_float(ed.y) * (float)__ldg(&g_cntN[ed.x]);
    }
    g_ye1[n] = s;
}
__global__ void k_dinvp_g(int KC) {
    int c = blockIdx.x * blockDim.x + threadIdx.x;
    if (c >= KC) return;
    int beg = g_offC[c], end = g_offC[c + 1];
    float s = 0.f;
    for (int j = beg; j < end; j++) s += __ldg(&g_ye1[g_cnC[j]]);
    g_dinvp[c] = rsqrtf(s + 1.0f);
}

// ---------------- sorted-label segment sum+max pooling (fp32 input) ----------------
__global__ void pool_sorted(const float* __restrict__ V, const int* __restrict__ lab,
                            float* __restrict__ S, float* __restrict__ X, int R, int chunk) {
    int t = threadIdx.x;
    long start = (long)blockIdx.x * chunk;
    if (start >= R) return;
    long end = start + chunk; if (end > R) end = R;
    int cur = __ldg(lab + start);
    float s = 0.f, m = 0.f;
    for (long r = start; r < end; r++) {
        int l = __ldg(lab + r);
        if (l != cur) {
            atomicAdd(&S[(size_t)cur * CH + t], s);
            atomicMax((unsigned int*)&X[(size_t)cur * CH + t], __float_as_uint(m));
            s = 0.f; m = 0.f; cur = l;
        }
        float v = __ldg(V + (size_t)r * CH + t);
        s += v; m = fmaxf(m, v);
    }
    atomicAdd(&S[(size_t)cur * CH + t], s);
    atomicMax((unsigned int*)&X[(size_t)cur * CH + t], __float_as_uint(m));
}

// ---------------- sorted-label segment sum+max pooling (fp16 input) ----------------
__global__ void pool_sorted_h(const __half* __restrict__ V, const int* __restrict__ lab,
                              float* __restrict__ S, float* __restrict__ X, int R, int chunk) {
    int t = threadIdx.x;
    long start = (long)blockIdx.x * chunk;
    if (start >= R) return;
    long end = start + chunk; if (end > R) end = R;
    int cur = __ldg(lab + start);
    float s = 0.f, m = 0.f;
    for (long r = start; r < end; r++) {
        int l = __ldg(lab + r);
        if (l != cur) {
            atomicAdd(&S[(size_t)cur * CH + t], s);
            atomicMax((unsigned int*)&X[(size_t)cur * CH + t], __float_as_uint(m));
            s = 0.f; m = 0.f; cur = l;
        }
        float v = __half2float(__ldg(V + (size_t)r * CH + t));
        s += v; m = fmaxf(m, v);
    }
    atomicAdd(&S[(size_t)cur * CH + t], s);
    atomicMax((unsigned int*)&X[(size_t)cur * CH + t], __float_as_uint(m));
}

// ---------------- cluster-batch counts via binary search ----------------
__global__ void k_ccounts_bs(const int* __restrict__ cb, int KC) {
    int b = threadIdx.x;
    if (b >= CB) return;
    int lo0 = 0, hi0 = KC;
    while (lo0 < hi0) { int mid = (lo0 + hi0) >> 1; if (__ldg(cb + mid) < b) lo0 = mid + 1; else hi0 = mid; }
    int lo1 = lo0, hi1 = KC;
    while (lo1 < hi1) { int mid = (lo1 + hi1) >> 1; if (__ldg(cb + mid) < b + 1) lo1 = mid + 1; else hi1 = mid; }
    g_cc[b] = (float)(lo1 - lo0);
}

// ================= 1xTF32 tensor-core GEMM (fp32/fp16 A, fp32/fp16 out) =================
#define SMS 136

__device__ __forceinline__ uint32_t f2tf32(float f) {
    uint32_t u;
    asm("cvt.rna.tf32.f32 %0, %1;" : "=r"(u) : "f"(f));
    return u;
}
__device__ __forceinline__ void mma_tf32(float c[4], uint32_t a0, uint32_t a1,
                                         uint32_t a2, uint32_t a3,
                                         uint32_t b0, uint32_t b1) {
    asm volatile(
        "mma.sync.aligned.m16n8k8.row.col.f32.tf32.tf32.f32 "
        "{%0,%1,%2,%3}, {%4,%5,%6,%7}, {%8,%9}, {%0,%1,%2,%3};"
        : "+f"(c[0]), "+f"(c[1]), "+f"(c[2]), "+f"(c[3])
        : "r"(a0), "r"(a1), "r"(a2), "r"(a3), "r"(b0), "r"(b1));
}

__global__ __launch_bounds__(256)
void gemm_tf32(const float* __restrict__ A, const __half* __restrict__ Ah,
               const float* __restrict__ B,
               float* __restrict__ C, __half* __restrict__ Ch,
               int M, int K, const float* __restrict__ rowscale) {
    __shared__ float As[32 * SMS];
    __shared__ float Bs[32 * SMS];
    int tid = threadIdx.x;
    int lane = tid & 31;
    int wid = tid >> 5;
    int wm = wid & 1;
    int wn = wid >> 1;
    int lr = lane >> 2;
    int lc = lane & 3;
    int rowBase = blockIdx.x * 128;

    float acc[4][4][4];
    #pragma unroll
    for (int i = 0; i < 4; i++)
        #pragma unroll
        for (int j = 0; j < 4; j++)
            #pragma unroll
            for (int r = 0; r < 4; r++) acc[i][j][r] = 0.f;

    int aRow = tid >> 3;
    int aK4  = (tid & 7) * 4;
    int bK   = tid >> 5;
    int bN4  = lane * 4;

    for (int kc = 0; kc < K; kc += 32) {
        #pragma unroll
        for (int p = 0; p < 4; p++) {
            int m = p * 32 + aRow;
            int gr = rowBase + m;
            float4 av = make_float4(0.f, 0.f, 0.f, 0.f);
            if (gr < M) {
                if (Ah) {
                    uint2 u = *(const uint2*)(Ah + (size_t)gr * K + kc + aK4);
                    float2 f0 = __half22float2(*(__half2*)&u.x);
                    float2 f1 = __half22float2(*(__half2*)&u.y);
                    av = make_float4(f0.x, f0.y, f1.x, f1.y);
                } else {
                    av = *(const float4*)(A + (size_t)gr * K + kc + aK4);
                }
            }
            As[(aK4 + 0) * SMS + m] = av.x;
            As[(aK4 + 1) * SMS + m] = av.y;
            As[(aK4 + 2) * SMS + m] = av.z;
            As[(aK4 + 3) * SMS + m] = av.w;
        }
        #pragma unroll
        for (int p = 0; p < 4; p++) {
            int k = p * 8 + bK;
            float4 bv = *(const float4*)(B + (size_t)(kc + k) * 128 + bN4);
            *(float4*)&Bs[k * SMS + bN4] = bv;
        }
        __syncthreads();

        #pragma unroll
        for (int ks = 0; ks < 4; ks++) {
            int k0 = ks * 8;
            uint32_t a[4][4];
            #pragma unroll
            for (int mi = 0; mi < 4; mi++) {
                int mb = wm * 64 + mi * 16;
                a[mi][0] = f2tf32(As[(k0 + lc) * SMS + mb + lr]);
                a[mi][1] = f2tf32(As[(k0 + lc) * SMS + mb + lr + 8]);
                a[mi][2] = f2tf32(As[(k0 + 4 + lc) * SMS + mb + lr]);
                a[mi][3] = f2tf32(As[(k0 + 4 + lc) * SMS + mb + lr + 8]);
            }
            uint32_t b[4][2];
            #pragma unroll
            for (int ni = 0; ni < 4; ni++) {
                int nb = wn * 32 + ni * 8;
                b[ni][0] = f2tf32(Bs[(k0 + lc) * SMS + nb + lr]);
                b[ni][1] = f2tf32(Bs[(k0 + 4 + lc) * SMS + nb + lr]);
            }
            #pragma unroll
            for (int mi = 0; mi < 4; mi++)
                #pragma unroll
                for (int ni = 0; ni < 4; ni++)
                    mma_tf32(acc[mi][ni], a[mi][0], a[mi][1], a[mi][2], a[mi][3],
                             b[ni][0], b[ni][1]);
        }
        __syncthreads();
    }

    #pragma unroll
    for (int mi = 0; mi < 4; mi++) {
        int r0 = rowBase + wm * 64 + mi * 16 + lr;
        int r1 = r0 + 8;
        float s0 = 1.f, s1 = 1.f;
        if (rowscale) {
            if (r0 < M) s0 = __ldg(rowscale + r0);
            if (r1 < M) s1 = __ldg(rowscale + r1);
        }
        #pragma unroll
        for (int ni = 0; ni < 4; ni++) {
            int col = wn * 32 + ni * 8 + lc * 2;
            if (Ch) {
                if (r0 < M) {
                    __half2 hv = __floats2half2_rn(acc[mi][ni][0] * s0, acc[mi][ni][1] * s0);
                    *(__half2*)(Ch + (size_t)r0 * 128 + col) = hv;
                }
                if (r1 < M) {
                    __half2 hv = __floats2half2_rn(acc[mi][ni][2] * s1, acc[mi][ni][3] * s1);
                    *(__half2*)(Ch + (size_t)r1 * 128 + col) = hv;
                }
            } else {
                if (r0 < M) {
                    float2 v = make_float2(acc[mi][ni][0] * s0, acc[mi][ni][1] * s0);
                    *(float2*)(C + (size_t)r0 * 128 + col) = v;
                }
                if (r1 < M) {
                    float2 v = make_float2(acc[mi][ni][2] * s1, acc[mi][ni][3] * s1);
                    *(float2*)(C + (size_t)r1 * 128 + col) = v;
                }
            }
        }
    }
}

// ---------------- final BN + MLP + softmax ----------------
__global__ void k_mlp(const float* __restrict__ gamma, const float* __restrict__ beta,
                      const float* __restrict__ mu, const float* __restrict__ var,
                      const float* __restrict__ W1, const float* __restrict__ b1,
                      const float* __restrict__ W2, const float* __restrict__ b2,
                      float* __restrict__ out) {
    __shared__ float zs[4 * CH];
    __shared__ float y1s[CH];
    __shared__ float lg[CCOUT];
    int b = blockIdx.x, t = threadIdx.x;
    float inv_cc = 1.0f / g_cc[b];
    float raws[4];
    raws[0] = g_Sh [b * CH + t];
    raws[1] = g_Xh [b * CH + t];
    raws[2] = g_Shp[b * CH + t] * inv_cc;
    raws[3] = g_Xhp[b * CH + t];
    #pragma unroll
    for (int seg = 0; seg < 4; seg++) {
        int idx = seg * CH + t;
        zs[idx] = (raws[seg] - mu[idx]) * rsqrtf(var[idx] + 1e-5f) * gamma[idx] + beta[idx];
    }
    __syncthreads();
    float acc = b1[t];
    for (int k = 0; k < 4 * CH; k++) acc += zs[k] * W1[(size_t)k * CH + t];
    y1s[t] = fmaxf(acc, 0.f);
    __syncthreads();
    if (t < CCOUT) {
        float a = b2[t];
        for (int j = 0; j < CH; j++) a += y1s[j] * W2[j * CCOUT + t];
        lg[t] = a;
    }
    __syncthreads();
    if (t == 0) {
        float mx = lg[0];
        for (int c = 1; c < CCOUT; c++) mx = fmaxf(mx, lg[c]);
        float e[CCOUT]; float sum = 0.f;
        for (int c = 0; c < CCOUT; c++) { e[c] = expf(lg[c] - mx); sum += e[c]; }
        for (int c = 0; c < CCOUT; c++) out[b * CCOUT + c] = e[c] / sum;
    }
}

// ---------------- host ----------------
extern "C" void kernel_launch(void* const* d_in, const int* in_sizes, int n_in,
                              void* d_out, int out_size) {
    const float* x     = (const float*)d_in[0];
    const int*   ei    = (const int*)  d_in[1];
    const float* w     = (const float*)d_in[2];
    const int*   batch = (const int*)  d_in[3];
    const int*   cn    = (const int*)  d_in[4];
    const int*   cc    = (const int*)  d_in[5];
    const int*   cb    = (const int*)  d_in[6];
    const float* W_in  = (const float*)d_in[7];
    const float* b_in  = (const float*)d_in[8];
    const float* W_blk = (const float*)d_in[9];
    const float* b_blk = (const float*)d_in[10];
    const float* gam   = (const float*)d_in[11];
    const float* bet   = (const float*)d_in[12];
    const float* mu    = (const float*)d_in[13];
    const float* var   = (const float*)d_in[14];
    const float* W1    = (const float*)d_in[15];
    const float* b1    = (const float*)d_in[16];
    const float* W2    = (const float*)d_in[17];
    const float* b2    = (const float*)d_in[18];
    float* out = (float*)d_out;

    int E  = in_sizes[2];
    int N  = in_sizes[3];
    int M  = in_sizes[4];
    int KC = in_sizes[6];
    const int* src = ei;
    const int* dst = ei + E;

    float *p_hp, *p_Sh, *p_Xh, *p_Shp, *p_Xhp, *p_dinvp, *p_deg;
    __half *p_xwh, *p_hh, *p_xph, *p_xwsh;
    int *p_cntE, *p_cntC, *p_cntN, *p_offE, *p_offC, *p_offN, *p_curE, *p_curC, *p_curN;
    cudaGetSymbolAddress((void**)&p_xwh,  g_xwh);
    cudaGetSymbolAddress((void**)&p_hh,   g_hh);
    cudaGetSymbolAddress((void**)&p_xph,  g_xph);
    cudaGetSymbolAddress((void**)&p_xwsh, g_xwsh);
    cudaGetSymbolAddress((void**)&p_hp,   g_hp);
    cudaGetSymbolAddress((void**)&p_Sh,   g_Sh);
    cudaGetSymbolAddress((void**)&p_Xh,   g_Xh);
    cudaGetSymbolAddress((void**)&p_Shp,  g_Shp);
    cudaGetSymbolAddress((void**)&p_Xhp,  g_Xhp);
    cudaGetSymbolAddress((void**)&p_dinvp, g_dinvp);
    cudaGetSymbolAddress((void**)&p_deg,  g_deg);
    cudaGetSymbolAddress((void**)&p_cntE, g_cntE);
    cudaGetSymbolAddress((void**)&p_cntC, g_cntC);
    cudaGetSymbolAddress((void**)&p_cntN, g_cntN);
    cudaGetSymbolAddress((void**)&p_offE, g_offE);
    cudaGetSymbolAddress((void**)&p_offC, g_offC);
    cudaGetSymbolAddress((void**)&p_offN, g_offN);
    cudaGetSymbolAddress((void**)&p_curE, g_curE);
    cudaGetSymbolAddress((void**)&p_curC, g_curC);
    cudaGetSymbolAddress((void**)&p_curN, g_curN);

    const int T = 256;
    int warpsN  = (int)(((long)N * 32 + T - 1) / T);
    int warpsKC = (int)(((long)KC * 32 + T - 1) / T);
    int bE = (N + SCAN_BS - 1) / SCAN_BS;
    int bC = (KC + SCAN_BS - 1) / SCAN_BS;
    int bN = (N + SCAN_BS - 1) / SCAN_BS;

    // ---- fork ----
    cudaEventRecord(hevStart, 0);

    // ===== s1: gemm1 (fp16 output), then aprime(ones) chain =====
    cudaStreamWaitEvent(hs1, hevStart, 0);
    gemm_tf32<<<(N + 127) / 128, 256, 0, hs1>>>(x, nullptr, W_in, nullptr, p_xwh, N, CH, nullptr);
    cudaEventRecord(hevGemm1, hs1);

    // ===== s2: C/N-side CSR build + pooling zeroing + ccounts =====
    cudaStreamWaitEvent(hs2, hevStart, 0);
    cudaMemsetAsync(p_cntC, 0, (size_t)KC * 4, hs2);
    cudaMemsetAsync(p_cntN, 0, (size_t)N * 4, hs2);
    cudaMemsetAsync(p_Sh,   0, (size_t)CB * CH * 4, hs2);
    cudaMemsetAsync(p_Xh,   0, (size_t)CB * CH * 4, hs2);
    cudaMemsetAsync(p_Shp,  0, (size_t)CB * CH * 4, hs2);
    cudaMemsetAsync(p_Xhp,  0, (size_t)CB * CH * 4, hs2);
    cudaEventRecord(hevZeroP, hs2);
    k_ccounts_bs<<<1, CB, 0, hs2>>>(cb, KC);
    k_histM<<<(M + T - 1) / T, T, 0, hs2>>>(cc, cn, M);
    k_scanA1<<<bC, 256, 0, hs2>>>(p_cntC, KC, 64);
    k_scanB1<<<1, 32, 0, hs2>>>(bC, 64, p_offC + KC);
    k_scanC1<<<bC, 256, 0, hs2>>>(p_cntC, p_offC, p_curC, KC, 64);
    k_scanA1<<<bN, 256, 0, hs2>>>(p_cntN, N, 128);
    k_scanB1<<<1, 32, 0, hs2>>>(bN, 128, p_offN + N);
    k_scanC1<<<bN, 256, 0, hs2>>>(p_cntN, p_offN, p_curN, N, 128);
    k_fillCN<<<(M + T - 1) / T, T, 0, hs2>>>(cn, cc, M);
    cudaEventRecord(hevFillCN, hs2);

    // ===== s0: E-side CSR build =====
    cudaMemsetAsync(p_cntE, 0, (size_t)N * 4, 0);
    cudaMemsetAsync(p_deg,  0, (size_t)N * 4, 0);
    k_histE<<<(E + T - 1) / T, T>>>(dst, E);
    k_scanA1<<<bE, 256>>>(p_cntE, N, 0);
    k_scanB1<<<1, 32>>>(bE, 0, p_offE + N);
    k_scanC1<<<bE, 256>>>(p_cntE, p_offE, p_curE, N, 0);
    k_fillE<<<(E + T - 1) / T, T>>>(src, dst, w, E);
    cudaEventRecord(hevFillE, 0);
    k_dinv<<<(N + T - 1) / T, T>>>(N);

    // s1: aprime(ones) chain (needs CSR-E + cntN/CSR-C)
    cudaStreamWaitEvent(hs1, hevFillE, 0);
    cudaStreamWaitEvent(hs1, hevFillCN, 0);
    k_ye1g   <<<(N + T - 1) / T, T, 0, hs1>>>(N);
    k_dinvp_g<<<(KC + T - 1) / T, T, 0, hs1>>>(KC);
    cudaEventRecord(hevDinvp, hs1);

    // s0: GCN pass 1 (needs xwh + CSR-E + dinv)
    cudaStreamWaitEvent(0, hevGemm1, 0);
    gather_gcn1<<<warpsN, T>>>(b_in, N);
    cudaEventRecord(hevH, 0);

    // s2: node pooling (after zeroing + ccounts on s2; needs hh)
    cudaStreamWaitEvent(hs2, hevH, 0);
    pool_sorted_h<<<(N + 127) / 128, CH, 0, hs2>>>(p_hh, batch, p_Sh, p_Xh, N, 128);
    cudaEventRecord(hevSide, hs2);

    // s0: cover pooling (fp16 out), gemm2 (fp16 A, fp16 out), aprime(xws) chain, hp, cluster pooling
    cudaStreamWaitEvent(0, hevFillCN, 0);
    gather_xp<<<warpsKC, T>>>(KC);
    cudaStreamWaitEvent(0, hevDinvp, 0);
    gemm_tf32<<<(KC + 127) / 128, 256>>>(nullptr, p_xph, W_blk, nullptr, p_xwsh, KC, 2 * CH, p_dinvp);
    gather_zn<<<warpsN, T>>>(N);
    gather_ye<<<warpsN, T>>>(N);
    gather_hp<<<warpsKC, T>>>(b_blk, KC);
    cudaStreamWaitEvent(0, hevZeroP, 0);
    pool_sorted<<<(KC + 127) / 128, CH>>>(p_hp, cb, p_Shp, p_Xhp, KC, 128);

    // ---- join + final ----
    cudaStreamWaitEvent(0, hevSide, 0);
    k_mlp<<<CB, CH>>>(gam, bet, mu, var, W1, b1, W2, b2, out);
}

// round 15
// speedup vs baseline: 1.0302x; 1.0302x over previous
#include <cuda_runtime.h>
#include <cuda_fp16.h>
#include <math.h>
#include <stdint.h>

// Problem constants (fixed by the dataset)
#define CN   100000
#define CE   1600000
#define CH   128
#define CM   150000
#define CKC  60000
#define CB   64
#define CCOUT 10

// ---------------- scratch (device globals; no allocation) ----------------
__device__ __align__(128) __half g_xwh [(size_t)CN * CH];    // fp16 x @ W_in
__device__ __align__(128) __half g_hh  [(size_t)CN * CH];    // fp16 relu(gcn1)
__device__ __align__(128) __half g_znh [(size_t)CN * CH];    // fp16 zn
__device__ __align__(128) __half g_yeh [(size_t)CN * CH];    // fp16 ye
__device__ __align__(128) __half g_xph [(size_t)CKC * 2 * CH]; // fp16 [add|max] cover pool
__device__ __align__(128) __half g_xwsh[(size_t)CKC * CH];   // fp16 dinvp*(xp@W_blk)
__device__ __align__(128) float g_hp  [(size_t)CKC * CH];
__device__ __align__(128) float g_deg  [CN];
__device__ __align__(128) float g_dinv [CN];
__device__ __align__(128) float g_ye1  [CN];
__device__ __align__(128) float g_dinvp[CKC];
__device__ __align__(128) float g_Sh [CB * CH];
__device__ __align__(128) float g_Xh [CB * CH];
__device__ __align__(128) float g_Shp[CB * CH];
__device__ __align__(128) float g_Xhp[CB * CH];
__device__ __align__(128) float g_cc [CB];

// CSR-E: dst -> (src, w)
__device__ __align__(128) int  g_cntE[CN];
__device__ __align__(128) int  g_offE[CN + 1];
__device__ __align__(128) int  g_curE[CN];
__device__ __align__(128) int2 g_edges[CE];
// CSR-C: cluster -> cover_node entries
__device__ __align__(128) int  g_cntC[CKC];
__device__ __align__(128) int  g_offC[CKC + 1];
__device__ __align__(128) int  g_curC[CKC];
__device__ __align__(128) int  g_cnC [CM];
// CSR-N: node -> cover_cluster entries
__device__ __align__(128) int  g_cntN[CN];
__device__ __align__(128) int  g_offN[CN + 1];
__device__ __align__(128) int  g_curN[CN];
__device__ __align__(128) int  g_ccN [CM];

// scan temporaries (bases: E=0, C=64, N=128; each needs <64 blocks)
__device__ int g_blockSums[256];
__device__ int g_blockOffs[256];

#define SCAN_BS 2048

// ---------------- process-lifetime streams/events ----------------
static cudaStream_t hs1, hs2;
static cudaEvent_t hevStart, hevGemm1, hevFillE, hevFillCN, hevH,
                   hevDinvp, hevZeroP, hevSide;
namespace {
struct StreamInit {
    StreamInit() {
        cudaStreamCreateWithFlags(&hs1, cudaStreamNonBlocking);
        cudaStreamCreateWithFlags(&hs2, cudaStreamNonBlocking);
        cudaEventCreateWithFlags(&hevStart,  cudaEventDisableTiming);
        cudaEventCreateWithFlags(&hevGemm1,  cudaEventDisableTiming);
        cudaEventCreateWithFlags(&hevFillE,  cudaEventDisableTiming);
        cudaEventCreateWithFlags(&hevFillCN, cudaEventDisableTiming);
        cudaEventCreateWithFlags(&hevH,      cudaEventDisableTiming);
        cudaEventCreateWithFlags(&hevDinvp,  cudaEventDisableTiming);
        cudaEventCreateWithFlags(&hevZeroP,  cudaEventDisableTiming);
        cudaEventCreateWithFlags(&hevSide,   cudaEventDisableTiming);
    }
};
static StreamInit s_init_;
}

// ---------------- histograms ----------------
__global__ void k_histE(const int* __restrict__ dst, int E) {
    int i = blockIdx.x * blockDim.x + threadIdx.x;
    if (i < E) atomicAdd(&g_cntE[dst[i]], 1);
}
__global__ void k_histM(const int* __restrict__ cc, const int* __restrict__ cn, int M) {
    int i = blockIdx.x * blockDim.x + threadIdx.x;
    if (i < M) {
        atomicAdd(&g_cntC[cc[i]], 1);
        atomicAdd(&g_cntN[cn[i]], 1);
    }
}

// ---------------- generic 3-phase scan ----------------
__global__ __launch_bounds__(256)
void k_scanA1(const int* __restrict__ cnt, int n, int base) {
    int t = threadIdx.x;
    int off0 = blockIdx.x * SCAN_BS + t * 8;
    int s = 0;
    #pragma unroll
    for (int k = 0; k < 8; k++) {
        int idx = off0 + k;
        if (idx < n) s += cnt[idx];
    }
    __shared__ int red[256];
    red[t] = s;
    __syncthreads();
    #pragma unroll
    for (int d = 128; d > 0; d >>= 1) {
        if (t < d) red[t] += red[t + d];
        __syncthreads();
    }
    if (t == 0) g_blockSums[base + blockIdx.x] = red[0];
}

__global__ void k_scanB1(int nb, int base, int* __restrict__ totalOut) {
    if (threadIdx.x == 0) {
        int run = 0;
        for (int i = 0; i < nb; i++) {
            int v = g_blockSums[base + i];
            g_blockOffs[base + i] = run;
            run += v;
        }
        *totalOut = run;
    }
}

__global__ __launch_bounds__(256)
void k_scanC1(const int* __restrict__ cnt, int* __restrict__ off, int* __restrict__ cur,
              int n, int base) {
    int t = threadIdx.x;
    int off0 = blockIdx.x * SCAN_BS + t * 8;
    int v[8];
    int s = 0;
    #pragma unroll
    for (int k = 0; k < 8; k++) {
        int idx = off0 + k;
        v[k] = (idx < n) ? cnt[idx] : 0;
        s += v[k];
    }
    __shared__ int red[256];
    red[t] = s;
    __syncthreads();
    #pragma unroll
    for (int d = 1; d < 256; d <<= 1) {
        int x = (t >= d) ? red[t - d] : 0;
        __syncthreads();
        red[t] += x;
        __syncthreads();
    }
    int pre = g_blockOffs[base + blockIdx.x] + red[t] - s;
    #pragma unroll
    for (int k = 0; k < 8; k++) {
        int idx = off0 + k;
        if (idx < n) { off[idx] = pre; cur[idx] = pre; }
        pre += v[k];
    }
}

// ---------------- CSR fills ----------------
__global__ void k_fillE(const int* __restrict__ src, const int* __restrict__ dst,
                        const float* __restrict__ w, int E) {
    int i = blockIdx.x * blockDim.x + threadIdx.x;
    if (i >= E) return;
    int d = dst[i];
    float wv = w[i];
    int pos = atomicAdd(&g_curE[d], 1);
    g_edges[pos] = make_int2(src[i], __float_as_int(wv));
    atomicAdd(&g_deg[d], wv);
}
__global__ void k_fillCN(const int* __restrict__ cn, const int* __restrict__ cc, int M) {
    int i = blockIdx.x * blockDim.x + threadIdx.x;
    if (i >= M) return;
    int node = cn[i], cl = cc[i];
    int pc = atomicAdd(&g_curC[cl], 1);
    g_cnC[pc] = node;
    int pn = atomicAdd(&g_curN[node], 1);
    g_ccN[pn] = cl;
}

__global__ void k_dinv(int N) {
    int i = blockIdx.x * blockDim.x + threadIdx.x;
    if (i < N) g_dinv[i] = rsqrtf(g_deg[i] + 1.0f);
}

// ---------------- fp16 helpers ----------------
__device__ __forceinline__ void fma_half_row(float4& acc, float c, uint2 u) {
    float2 f0 = __half22float2(*(__half2*)&u.x);
    float2 f1 = __half22float2(*(__half2*)&u.y);
    acc.x = fmaf(c, f0.x, acc.x); acc.y = fmaf(c, f0.y, acc.y);
    acc.z = fmaf(c, f1.x, acc.z); acc.w = fmaf(c, f1.y, acc.w);
}
__device__ __forceinline__ uint2 pack_half4(float4 v) {
    __half2 h0 = __floats2half2_rn(v.x, v.y);
    __half2 h1 = __floats2half2_rn(v.z, v.w);
    uint2 u;
    u.x = *(uint32_t*)&h0;
    u.y = *(uint32_t*)&h1;
    return u;
}

// ---------------- GCN pass 1 gather (fp16 rows, HFMA2 accumulation) ----------------
__global__ void gather_gcn1(const float* __restrict__ b_in, int N) {
    int wid = (blockIdx.x * blockDim.x + threadIdx.x) >> 5;
    if (wid >= N) return;
    int lane = threadIdx.x & 31;
    int beg = __ldg(&g_offE[wid]), end = __ldg(&g_offE[wid + 1]);
    float dn = __ldg(&g_dinv[wid]);
    __half2 acc0 = __float2half2_rn(0.f);
    __half2 acc1 = __float2half2_rn(0.f);
    int e = beg;
    for (; e + 8 <= end; e += 8) {
        int2 ed[8];
        #pragma unroll
        for (int q = 0; q < 8; q++) ed[q] = __ldg(&g_edges[e + q]);
        uint2 u[8];
        #pragma unroll
        for (int q = 0; q < 8; q++)
            u[q] = __ldg((const uint2*)(g_xwh + (size_t)ed[q].x * CH) + lane);
        #pragma unroll
        for (int q = 0; q < 8; q++) {
            float c = __int_as_float(ed[q].y) * dn * __ldg(&g_dinv[ed[q].x]);
            __half2 ch = __float2half2_rn(c);
            acc0 = __hfma2(ch, *(__half2*)&u[q].x, acc0);
            acc1 = __hfma2(ch, *(__half2*)&u[q].y, acc1);
        }
    }
    for (; e < end; e++) {
        int2 e0 = __ldg(&g_edges[e]);
        float c0 = __int_as_float(e0.y) * dn * __ldg(&g_dinv[e0.x]);
        uint2 u0 = __ldg((const uint2*)(g_xwh + (size_t)e0.x * CH) + lane);
        __half2 ch = __float2half2_rn(c0);
        acc0 = __hfma2(ch, *(__half2*)&u0.x, acc0);
        acc1 = __hfma2(ch, *(__half2*)&u0.y, acc1);
    }
    // convert to float for the self/bias/relu epilogue
    float2 a0 = __half22float2(acc0);
    float2 a1 = __half22float2(acc1);
    float4 acc = make_float4(a0.x, a0.y, a1.x, a1.y);
    uint2 us = __ldg((const uint2*)(g_xwh + (size_t)wid * CH) + lane);
    float2 s0 = __half22float2(*(__half2*)&us.x);
    float2 s1 = __half22float2(*(__half2*)&us.y);
    float4 bv = __ldg((const float4*)b_in + lane);
    float dd = dn * dn;
    acc.x = fmaxf(fmaf(dd, s0.x, acc.x) + bv.x, 0.f);
    acc.y = fmaxf(fmaf(dd, s0.y, acc.y) + bv.y, 0.f);
    acc.z = fmaxf(fmaf(dd, s1.x, acc.z) + bv.z, 0.f);
    acc.w = fmaxf(fmaf(dd, s1.y, acc.w) + bv.w, 0.f);
    *((uint2*)(g_hh + (size_t)wid * CH) + lane) = pack_half4(acc);
}

// ---------------- GCN pass 2 gather (fp16, HFMA2, covered-only) ----------------
__global__ void gather_ye(int N) {
    int wid = (blockIdx.x * blockDim.x + threadIdx.x) >> 5;
    if (wid >= N) return;
    if (__ldg(&g_offN[wid]) == __ldg(&g_offN[wid + 1])) return;
    int lane = threadIdx.x & 31;
    int beg = __ldg(&g_offE[wid]), end = __ldg(&g_offE[wid + 1]);
    __half2 acc0 = __float2half2_rn(0.f);
    __half2 acc1 = __float2half2_rn(0.f);
    int e = beg;
    for (; e + 8 <= end; e += 8) {
        int2 ed[8];
        #pragma unroll
        for (int q = 0; q < 8; q++) ed[q] = __ldg(&g_edges[e + q]);
        uint2 u[8];
        #pragma unroll
        for (int q = 0; q < 8; q++)
            u[q] = __ldg((const uint2*)(g_znh + (size_t)ed[q].x * CH) + lane);
        #pragma unroll
        for (int q = 0; q < 8; q++) {
            __half2 ch = __float2half2_rn(__int_as_float(ed[q].y));
            acc0 = __hfma2(ch, *(__half2*)&u[q].x, acc0);
            acc1 = __hfma2(ch, *(__half2*)&u[q].y, acc1);
        }
    }
    for (; e < end; e++) {
        int2 e0 = __ldg(&g_edges[e]);
        uint2 u0 = __ldg((const uint2*)(g_znh + (size_t)e0.x * CH) + lane);
        __half2 ch = __float2half2_rn(__int_as_float(e0.y));
        acc0 = __hfma2(ch, *(__half2*)&u0.x, acc0);
        acc1 = __hfma2(ch, *(__half2*)&u0.y, acc1);
    }
    uint2 outv;
    outv.x = *(uint32_t*)&acc0;
    outv.y = *(uint32_t*)&acc1;
    *((uint2*)(g_yeh + (size_t)wid * CH) + lane) = outv;
}

// ---------------- cover pooling gather (fp16 h in, fp16 xp out) ----------------
__global__ void gather_xp(int KC) {
    int wid = (blockIdx.x * blockDim.x + threadIdx.x) >> 5;
    if (wid >= KC) return;
    int lane = threadIdx.x & 31;
    int beg = __ldg(&g_offC[wid]), end = __ldg(&g_offC[wid + 1]);
    float4 add = make_float4(0.f, 0.f, 0.f, 0.f);
    float4 mx  = make_float4(0.f, 0.f, 0.f, 0.f);
    for (int j = beg; j < end; j++) {
        int node = __ldg(&g_cnC[j]);
        uint2 u = __ldg((const uint2*)(g_hh + (size_t)node * CH) + lane);
        float2 f0 = __half22float2(*(__half2*)&u.x);
        float2 f1 = __half22float2(*(__half2*)&u.y);
        add.x += f0.x; add.y += f0.y; add.z += f1.x; add.w += f1.y;
        mx.x = fmaxf(mx.x, f0.x); mx.y = fmaxf(mx.y, f0.y);
        mx.z = fmaxf(mx.z, f1.x); mx.w = fmaxf(mx.w, f1.y);
    }
    __half* xp = g_xph + (size_t)wid * (2 * CH);
    *((uint2*)xp + lane) = pack_half4(add);
    *((uint2*)(xp + CH) + lane) = pack_half4(mx);
}

// ---------------- zn = C xws gather (fp16 xws in), store fp16 ----------------
__global__ void gather_zn(int N) {
    int wid = (blockIdx.x * blockDim.x + threadIdx.x) >> 5;
    if (wid >= N) return;
    int lane = threadIdx.x & 31;
    int beg = __ldg(&g_offN[wid]), end = __ldg(&g_offN[wid + 1]);
    float4 acc = make_float4(0.f, 0.f, 0.f, 0.f);
    for (int j = beg; j < end; j++) {
        int cl = __ldg(&g_ccN[j]);
        uint2 u = __ldg((const uint2*)(g_xwsh + (size_t)cl * CH) + lane);
        fma_half_row(acc, 1.0f, u);
    }
    *((uint2*)(g_znh + (size_t)wid * CH) + lane) = pack_half4(acc);
}

// ---------------- hp gather (fp16 ye + fp16 xws in) ----------------
__global__ void gather_hp(const float* __restrict__ b_blk, int KC) {
    int wid = (blockIdx.x * blockDim.x + threadIdx.x) >> 5;
    if (wid >= KC) return;
    int lane = threadIdx.x & 31;
    int beg = __ldg(&g_offC[wid]), end = __ldg(&g_offC[wid + 1]);
    float4 acc = make_float4(0.f, 0.f, 0.f, 0.f);
    for (int j = beg; j < end; j++) {
        int node = __ldg(&g_cnC[j]);
        uint2 u = __ldg((const uint2*)(g_yeh + (size_t)node * CH) + lane);
        fma_half_row(acc, 1.0f, u);
    }
    float dp = __ldg(&g_dinvp[wid]);
    uint2 ux = __ldg((const uint2*)(g_xwsh + (size_t)wid * CH) + lane);
    float2 x0 = __half22float2(*(__half2*)&ux.x);
    float2 x1 = __half22float2(*(__half2*)&ux.y);
    float4 bv = __ldg((const float4*)b_blk + lane);
    acc.x = fmaxf(fmaf(dp, acc.x + x0.x, bv.x), 0.f);
    acc.y = fmaxf(fmaf(dp, acc.y + x0.y, bv.y), 0.f);
    acc.z = fmaxf(fmaf(dp, acc.z + x1.x, bv.z), 0.f);
    acc.w = fmaxf(fmaf(dp, acc.w + x1.y, bv.w), 0.f);
    *((float4*)(g_hp + (size_t)wid * CH) + lane) = acc;
}

// ---------------- aprime(ones) scalar chain ----------------
__global__ void k_ye1g(int N) {
    int n = blockIdx.x * blockDim.x + threadIdx.x;
    if (n >= N) return;
    int beg = g_offE[n], end = g_offE[n + 1];
    float s = 0.f;
    for (int e = beg; e < end; e++) {
        int2 ed = __ldg(&g_edges[e]);
        s += __int_as_float(ed.y) * (float)__ldg(&g_cntN[ed.x]);
    }
    g_ye1[n] = s;
}
__global__ void k_dinvp_g(int KC) {
    int c = blockIdx.x * blockDim.x + threadIdx.x;
    if (c >= KC) return;
    int beg = g_offC[c], end = g_offC[c + 1];
    float s = 0.f;
    for (int j = beg; j < end; j++) s += __ldg(&g_ye1[g_cnC[j]]);
    g_dinvp[c] = rsqrtf(s + 1.0f);
}

// ---------------- sorted-label segment sum+max pooling (fp32 input) ----------------
__global__ void pool_sorted(const float* __restrict__ V, const int* __restrict__ lab,
                            float* __restrict__ S, float* __restrict__ X, int R, int chunk) {
    int t = threadIdx.x;
    long start = (long)blockIdx.x * chunk;
    if (start >= R) return;
    long end = start + chunk; if (end > R) end = R;
    int cur = __ldg(lab + start);
    float s = 0.f, m = 0.f;
    for (long r = start; r < end; r++) {
        int l = __ldg(lab + r);
        if (l != cur) {
            atomicAdd(&S[(size_t)cur * CH + t], s);
            atomicMax((unsigned int*)&X[(size_t)cur * CH + t], __float_as_uint(m));
            s = 0.f; m = 0.f; cur = l;
        }
        float v = __ldg(V + (size_t)r * CH + t);
        s += v; m = fmaxf(m, v);
    }
    atomicAdd(&S[(size_t)cur * CH + t], s);
    atomicMax((unsigned int*)&X[(size_t)cur * CH + t], __float_as_uint(m));
}

// ---------------- sorted-label segment sum+max pooling (fp16 input) ----------------
__global__ void pool_sorted_h(const __half* __restrict__ V, const int* __restrict__ lab,
                              float* __restrict__ S, float* __restrict__ X, int R, int chunk) {
    int t = threadIdx.x;
    long start = (long)blockIdx.x * chunk;
    if (start >= R) return;
    long end = start + chunk; if (end > R) end = R;
    int cur = __ldg(lab + start);
    float s = 0.f, m = 0.f;
    for (long r = start; r < end; r++) {
        int l = __ldg(lab + r);
        if (l != cur) {
            atomicAdd(&S[(size_t)cur * CH + t], s);
            atomicMax((unsigned int*)&X[(size_t)cur * CH + t], __float_as_uint(m));
            s = 0.f; m = 0.f; cur = l;
        }
        float v = __half2float(__ldg(V + (size_t)r * CH + t));
        s += v; m = fmaxf(m, v);
    }
    atomicAdd(&S[(size_t)cur * CH + t], s);
    atomicMax((unsigned int*)&X[(size_t)cur * CH + t], __float_as_uint(m));
}

// ---------------- cluster-batch counts via binary search ----------------
__global__ void k_ccounts_bs(const int* __restrict__ cb, int KC) {
    int b = threadIdx.x;
    if (b >= CB) return;
    int lo0 = 0, hi0 = KC;
    while (lo0 < hi0) { int mid = (lo0 + hi0) >> 1; if (__ldg(cb + mid) < b) lo0 = mid + 1; else hi0 = mid; }
    int lo1 = lo0, hi1 = KC;
    while (lo1 < hi1) { int mid = (lo1 + hi1) >> 1; if (__ldg(cb + mid) < b + 1) lo1 = mid + 1; else hi1 = mid; }
    g_cc[b] = (float)(lo1 - lo0);
}

// ================= 1xTF32 tensor-core GEMM (fp32/fp16 A, fp32/fp16 out) =================
#define SMS 136

__device__ __forceinline__ uint32_t f2tf32(float f) {
    uint32_t u;
    asm("cvt.rna.tf32.f32 %0, %1;" : "=r"(u) : "f"(f));
    return u;
}
__device__ __forceinline__ void mma_tf32(float c[4], uint32_t a0, uint32_t a1,
                                         uint32_t a2, uint32_t a3,
                                         uint32_t b0, uint32_t b1) {
    asm volatile(
        "mma.sync.aligned.m16n8k8.row.col.f32.tf32.tf32.f32 "
        "{%0,%1,%2,%3}, {%4,%5,%6,%7}, {%8,%9}, {%0,%1,%2,%3};"
        : "+f"(c[0]), "+f"(c[1]), "+f"(c[2]), "+f"(c[3])
        : "r"(a0), "r"(a1), "r"(a2), "r"(a3), "r"(b0), "r"(b1));
}

__global__ __launch_bounds__(256)
void gemm_tf32(const float* __restrict__ A, const __half* __restrict__ Ah,
               const float* __restrict__ B,
               float* __restrict__ C, __half* __restrict__ Ch,
               int M, int K, const float* __restrict__ rowscale) {
    __shared__ float As[32 * SMS];
    __shared__ float Bs[32 * SMS];
    int tid = threadIdx.x;
    int lane = tid & 31;
    int wid = tid >> 5;
    int wm = wid & 1;
    int wn = wid >> 1;
    int lr = lane >> 2;
    int lc = lane & 3;
    int rowBase = blockIdx.x * 128;

    float acc[4][4][4];
    #pragma unroll
    for (int i = 0; i < 4; i++)
        #pragma unroll
        for (int j = 0; j < 4; j++)
            #pragma unroll
            for (int r = 0; r < 4; r++) acc[i][j][r] = 0.f;

    int aRow = tid >> 3;
    int aK4  = (tid & 7) * 4;
    int bK   = tid >> 5;
    int bN4  = lane * 4;

    for (int kc = 0; kc < K; kc += 32) {
        #pragma unroll
        for (int p = 0; p < 4; p++) {
            int m = p * 32 + aRow;
            int gr = rowBase + m;
            float4 av = make_float4(0.f, 0.f, 0.f, 0.f);
            if (gr < M) {
                if (Ah) {
                    uint2 u = *(const uint2*)(Ah + (size_t)gr * K + kc + aK4);
                    float2 f0 = __half22float2(*(__half2*)&u.x);
                    float2 f1 = __half22float2(*(__half2*)&u.y);
                    av = make_float4(f0.x, f0.y, f1.x, f1.y);
                } else {
                    av = *(const float4*)(A + (size_t)gr * K + kc + aK4);
                }
            }
            As[(aK4 + 0) * SMS + m] = av.x;
            As[(aK4 + 1) * SMS + m] = av.y;
            As[(aK4 + 2) * SMS + m] = av.z;
            As[(aK4 + 3) * SMS + m] = av.w;
        }
        #pragma unroll
        for (int p = 0; p < 4; p++) {
            int k = p * 8 + bK;
            float4 bv = *(const float4*)(B + (size_t)(kc + k) * 128 + bN4);
            *(float4*)&Bs[k * SMS + bN4] = bv;
        }
        __syncthreads();

        #pragma unroll
        for (int ks = 0; ks < 4; ks++) {
            int k0 = ks * 8;
            uint32_t a[4][4];
            #pragma unroll
            for (int mi = 0; mi < 4; mi++) {
                int mb = wm * 64 + mi * 16;
                a[mi][0] = f2tf32(As[(k0 + lc) * SMS + mb + lr]);
                a[mi][1] = f2tf32(As[(k0 + lc) * SMS + mb + lr + 8]);
                a[mi][2] = f2tf32(As[(k0 + 4 + lc) * SMS + mb + lr]);
                a[mi][3] = f2tf32(As[(k0 + 4 + lc) * SMS + mb + lr + 8]);
            }
            uint32_t b[4][2];
            #pragma unroll
            for (int ni = 0; ni < 4; ni++) {
                int nb = wn * 32 + ni * 8;
                b[ni][0] = f2tf32(Bs[(k0 + lc) * SMS + nb + lr]);
                b[ni][1] = f2tf32(Bs[(k0 + 4 + lc) * SMS + nb + lr]);
            }
            #pragma unroll
            for (int mi = 0; mi < 4; mi++)
                #pragma unroll
                for (int ni = 0; ni < 4; ni++)
                    mma_tf32(acc[mi][ni], a[mi][0], a[mi][1], a[mi][2], a[mi][3],
                             b[ni][0], b[ni][1]);
        }
        __syncthreads();
    }

    #pragma unroll
    for (int mi = 0; mi < 4; mi++) {
        int r0 = rowBase + wm * 64 + mi * 16 + lr;
        int r1 = r0 + 8;
        float s0 = 1.f, s1 = 1.f;
        if (rowscale) {
            if (r0 < M) s0 = __ldg(rowscale + r0);
            if (r1 < M) s1 = __ldg(rowscale + r1);
        }
        #pragma unroll
        for (int ni = 0; ni < 4; ni++) {
            int col = wn * 32 + ni * 8 + lc * 2;
            if (Ch) {
                if (r0 < M) {
                    __half2 hv = __floats2half2_rn(acc[mi][ni][0] * s0, acc[mi][ni][1] * s0);
                    *(__half2*)(Ch + (size_t)r0 * 128 + col) = hv;
                }
                if (r1 < M) {
                    __half2 hv = __floats2half2_rn(acc[mi][ni][2] * s1, acc[mi][ni][3] * s1);
                    *(__half2*)(Ch + (size_t)r1 * 128 + col) = hv;
                }
            } else {
                if (r0 < M) {
                    float2 v = make_float2(acc[mi][ni][0] * s0, acc[mi][ni][1] * s0);
                    *(float2*)(C + (size_t)r0 * 128 + col) = v;
                }
                if (r1 < M) {
                    float2 v = make_float2(acc[mi][ni][2] * s1, acc[mi][ni][3] * s1);
                    *(float2*)(C + (size_t)r1 * 128 + col) = v;
                }
            }
        }
    }
}

// ---------------- final BN + MLP + softmax ----------------
__global__ void k_mlp(const float* __restrict__ gamma, const float* __restrict__ beta,
                      const float* __restrict__ mu, const float* __restrict__ var,
                      const float* __restrict__ W1, const float* __restrict__ b1,
                      const float* __restrict__ W2, const float* __restrict__ b2,
                      float* __restrict__ out) {
    __shared__ float zs[4 * CH];
    __shared__ float y1s[CH];
    __shared__ float lg[CCOUT];
    int b = blockIdx.x, t = threadIdx.x;
    float inv_cc = 1.0f / g_cc[b];
    float raws[4];
    raws[0] = g_Sh [b * CH + t];
    raws[1] = g_Xh [b * CH + t];
    raws[2] = g_Shp[b * CH + t] * inv_cc;
    raws[3] = g_Xhp[b * CH + t];
    #pragma unroll
    for (int seg = 0; seg < 4; seg++) {
        int idx = seg * CH + t;
        zs[idx] = (raws[seg] - mu[idx]) * rsqrtf(var[idx] + 1e-5f) * gamma[idx] + beta[idx];
    }
    __syncthreads();
    float acc = b1[t];
    for (int k = 0; k < 4 * CH; k++) acc += zs[k] * W1[(size_t)k * CH + t];
    y1s[t] = fmaxf(acc, 0.f);
    __syncthreads();
    if (t < CCOUT) {
        float a = b2[t];
        for (int j = 0; j < CH; j++) a += y1s[j] * W2[j * CCOUT + t];
        lg[t] = a;
    }
    __syncthreads();
    if (t == 0) {
        float mx = lg[0];
        for (int c = 1; c < CCOUT; c++) mx = fmaxf(mx, lg[c]);
        float e[CCOUT]; float sum = 0.f;
        for (int c = 0; c < CCOUT; c++) { e[c] = expf(lg[c] - mx); sum += e[c]; }
        for (int c = 0; c < CCOUT; c++) out[b * CCOUT + c] = e[c] / sum;
    }
}

// ---------------- host ----------------
extern "C" void kernel_launch(void* const* d_in, const int* in_sizes, int n_in,
                              void* d_out, int out_size) {
    const float* x     = (const float*)d_in[0];
    const int*   ei    = (const int*)  d_in[1];
    const float* w     = (const float*)d_in[2];
    const int*   batch = (const int*)  d_in[3];
    const int*   cn    = (const int*)  d_in[4];
    const int*   cc    = (const int*)  d_in[5];
    const int*   cb    = (const int*)  d_in[6];
    const float* W_in  = (const float*)d_in[7];
    const float* b_in  = (const float*)d_in[8];
    const float* W_blk = (const float*)d_in[9];
    const float* b_blk = (const float*)d_in[10];
    const float* gam   = (const float*)d_in[11];
    const float* bet   = (const float*)d_in[12];
    const float* mu    = (const float*)d_in[13];
    const float* var   = (const float*)d_in[14];
    const float* W1    = (const float*)d_in[15];
    const float* b1    = (const float*)d_in[16];
    const float* W2    = (const float*)d_in[17];
    const float* b2    = (const float*)d_in[18];
    float* out = (float*)d_out;

    int E  = in_sizes[2];
    int N  = in_sizes[3];
    int M  = in_sizes[4];
    int KC = in_sizes[6];
    const int* src = ei;
    const int* dst = ei + E;

    float *p_hp, *p_Sh, *p_Xh, *p_Shp, *p_Xhp, *p_dinvp, *p_deg;
    __half *p_xwh, *p_hh, *p_xph, *p_xwsh;
    int *p_cntE, *p_cntC, *p_cntN, *p_offE, *p_offC, *p_offN, *p_curE, *p_curC, *p_curN;
    cudaGetSymbolAddress((void**)&p_xwh,  g_xwh);
    cudaGetSymbolAddress((void**)&p_hh,   g_hh);
    cudaGetSymbolAddress((void**)&p_xph,  g_xph);
    cudaGetSymbolAddress((void**)&p_xwsh, g_xwsh);
    cudaGetSymbolAddress((void**)&p_hp,   g_hp);
    cudaGetSymbolAddress((void**)&p_Sh,   g_Sh);
    cudaGetSymbolAddress((void**)&p_Xh,   g_Xh);
    cudaGetSymbolAddress((void**)&p_Shp,  g_Shp);
    cudaGetSymbolAddress((void**)&p_Xhp,  g_Xhp);
    cudaGetSymbolAddress((void**)&p_dinvp, g_dinvp);
    cudaGetSymbolAddress((void**)&p_deg,  g_deg);
    cudaGetSymbolAddress((void**)&p_cntE, g_cntE);
    cudaGetSymbolAddress((void**)&p_cntC, g_cntC);
    cudaGetSymbolAddress((void**)&p_cntN, g_cntN);
    cudaGetSymbolAddress((void**)&p_offE, g_offE);
    cudaGetSymbolAddress((void**)&p_offC, g_offC);
    cudaGetSymbolAddress((void**)&p_offN, g_offN);
    cudaGetSymbolAddress((void**)&p_curE, g_curE);
    cudaGetSymbolAddress((void**)&p_curC, g_curC);
    cudaGetSymbolAddress((void**)&p_curN, g_curN);

    const int T = 256;
    int warpsN  = (int)(((long)N * 32 + T - 1) / T);
    int warpsKC = (int)(((long)KC * 32 + T - 1) / T);
    int bE = (N + SCAN_BS - 1) / SCAN_BS;
    int bC = (KC + SCAN_BS - 1) / SCAN_BS;
    int bN = (N + SCAN_BS - 1) / SCAN_BS;

    // ---- fork ----
    cudaEventRecord(hevStart, 0);

    // ===== s1: gemm1 (fp16 output), then aprime(ones) chain =====
    cudaStreamWaitEvent(hs1, hevStart, 0);
    gemm_tf32<<<(N + 127) / 128, 256, 0, hs1>>>(x, nullptr, W_in, nullptr, p_xwh, N, CH, nullptr);
    cudaEventRecord(hevGemm1, hs1);

    // ===== s2: C/N-side CSR build + pooling zeroing + ccounts =====
    cudaStreamWaitEvent(hs2, hevStart, 0);
    cudaMemsetAsync(p_cntC, 0, (size_t)KC * 4, hs2);
    cudaMemsetAsync(p_cntN, 0, (size_t)N * 4, hs2);
    cudaMemsetAsync(p_Sh,   0, (size_t)CB * CH * 4, hs2);
    cudaMemsetAsync(p_Xh,   0, (size_t)CB * CH * 4, hs2);
    cudaMemsetAsync(p_Shp,  0, (size_t)CB * CH * 4, hs2);
    cudaMemsetAsync(p_Xhp,  0, (size_t)CB * CH * 4, hs2);
    cudaEventRecord(hevZeroP, hs2);
    k_ccounts_bs<<<1, CB, 0, hs2>>>(cb, KC);
    k_histM<<<(M + T - 1) / T, T, 0, hs2>>>(cc, cn, M);
    k_scanA1<<<bC, 256, 0, hs2>>>(p_cntC, KC, 64);
    k_scanB1<<<1, 32, 0, hs2>>>(bC, 64, p_offC + KC);
    k_scanC1<<<bC, 256, 0, hs2>>>(p_cntC, p_offC, p_curC, KC, 64);
    k_scanA1<<<bN, 256, 0, hs2>>>(p_cntN, N, 128);
    k_scanB1<<<1, 32, 0, hs2>>>(bN, 128, p_offN + N);
    k_scanC1<<<bN, 256, 0, hs2>>>(p_cntN, p_offN, p_curN, N, 128);
    k_fillCN<<<(M + T - 1) / T, T, 0, hs2>>>(cn, cc, M);
    cudaEventRecord(hevFillCN, hs2);

    // ===== s0: E-side CSR build =====
    cudaMemsetAsync(p_cntE, 0, (size_t)N * 4, 0);
    cudaMemsetAsync(p_deg,  0, (size_t)N * 4, 0);
    k_histE<<<(E + T - 1) / T, T>>>(dst, E);
    k_scanA1<<<bE, 256>>>(p_cntE, N, 0);
    k_scanB1<<<1, 32>>>(bE, 0, p_offE + N);
    k_scanC1<<<bE, 256>>>(p_cntE, p_offE, p_curE, N, 0);
    k_fillE<<<(E + T - 1) / T, T>>>(src, dst, w, E);
    cudaEventRecord(hevFillE, 0);
    k_dinv<<<(N + T - 1) / T, T>>>(N);

    // s1: aprime(ones) chain (needs CSR-E + cntN/CSR-C)
    cudaStreamWaitEvent(hs1, hevFillE, 0);
    cudaStreamWaitEvent(hs1, hevFillCN, 0);
    k_ye1g   <<<(N + T - 1) / T, T, 0, hs1>>>(N);
    k_dinvp_g<<<(KC + T - 1) / T, T, 0, hs1>>>(KC);
    cudaEventRecord(hevDinvp, hs1);

    // s0: GCN pass 1 (needs xwh + CSR-E + dinv)
    cudaStreamWaitEvent(0, hevGemm1, 0);
    gather_gcn1<<<warpsN, T>>>(b_in, N);
    cudaEventRecord(hevH, 0);

    // s2: node pooling (after zeroing + ccounts on s2; needs hh)
    cudaStreamWaitEvent(hs2, hevH, 0);
    pool_sorted_h<<<(N + 127) / 128, CH, 0, hs2>>>(p_hh, batch, p_Sh, p_Xh, N, 128);
    cudaEventRecord(hevSide, hs2);

    // s0: cover pooling (fp16 out), gemm2 (fp16 A, fp16 out), aprime(xws) chain, hp, cluster pooling
    cudaStreamWaitEvent(0, hevFillCN, 0);
    gather_xp<<<warpsKC, T>>>(KC);
    cudaStreamWaitEvent(0, hevDinvp, 0);
    gemm_tf32<<<(KC + 127) / 128, 256>>>(nullptr, p_xph, W_blk, nullptr, p_xwsh, KC, 2 * CH, p_dinvp);
    gather_zn<<<warpsN, T>>>(N);
    gather_ye<<<warpsN, T>>>(N);
    gather_hp<<<warpsKC, T>>>(b_blk, KC);
    cudaStreamWaitEvent(0, hevZeroP, 0);
    pool_sorted<<<(KC + 127) / 128, CH>>>(p_hp, cb, p_Shp, p_Xhp, KC, 128);

    // ---- join + final ----
    cudaStreamWaitEvent(0, hevSide, 0);
    k_mlp<<<CB, CH>>>(gam, bet, mu, var, W1, b1, W2, b2, out);
}

// round 16
// speedup vs baseline: 1.0369x; 1.0064x over previous
#include <cuda_runtime.h>
#include <cuda_fp16.h>
#include <math.h>
#include <stdint.h>

// Problem constants (fixed by the dataset)
#define CN   100000
#define CE   1600000
#define CH   128
#define CM   150000
#define CKC  60000
#define CB   64
#define CCOUT 10

// ---------------- scratch (device globals; no allocation) ----------------
__device__ __align__(128) __half g_xwh [(size_t)CN * CH];    // fp16 x @ W_in
__device__ __align__(128) __half g_hh  [(size_t)CN * CH];    // fp16 relu(gcn1)
__device__ __align__(128) __half g_znh [(size_t)CN * CH];    // fp16 zn
__device__ __align__(128) __half g_yeh [(size_t)CN * CH];    // fp16 ye
__device__ __align__(128) __half g_xph [(size_t)CKC * 2 * CH]; // fp16 [add|max] cover pool
__device__ __align__(128) __half g_xwsh[(size_t)CKC * CH];   // fp16 dinvp*(xp@W_blk)
__device__ __align__(128) __half g_hph [(size_t)CKC * CH];   // fp16 hp
__device__ __align__(128) float g_deg  [CN];
__device__ __align__(128) float g_dinv [CN];
__device__ __align__(128) float g_ye1  [CN];
__device__ __align__(128) float g_dinvp[CKC];
__device__ __align__(128) float g_Sh [CB * CH];
__device__ __align__(128) float g_Xh [CB * CH];
__device__ __align__(128) float g_Shp[CB * CH];
__device__ __align__(128) float g_Xhp[CB * CH];
__device__ __align__(128) float g_cc [CB];

// CSR-E: dst -> (src, w)
__device__ __align__(128) int  g_cntE[CN];
__device__ __align__(128) int  g_offE[CN + 1];
__device__ __align__(128) int  g_curE[CN];
__device__ __align__(128) int2 g_edges[CE];
// CSR-C: cluster -> cover_node entries
__device__ __align__(128) int  g_cntC[CKC];
__device__ __align__(128) int  g_offC[CKC + 1];
__device__ __align__(128) int  g_curC[CKC];
__device__ __align__(128) int  g_cnC [CM];
// CSR-N: node -> cover_cluster entries
__device__ __align__(128) int  g_cntN[CN];
__device__ __align__(128) int  g_offN[CN + 1];
__device__ __align__(128) int  g_curN[CN];
__device__ __align__(128) int  g_ccN [CM];

// scan temporaries (bases: E=0, C=64, N=128; each needs <64 blocks)
__device__ int g_blockSums[256];
__device__ int g_blockOffs[256];

#define SCAN_BS 2048

// ---------------- process-lifetime streams/events ----------------
static cudaStream_t hs1, hs2;
static cudaEvent_t hevStart, hevGemm1, hevFillE, hevFillCN, hevH,
                   hevDinvp, hevZeroP, hevSide;
namespace {
struct StreamInit {
    StreamInit() {
        cudaStreamCreateWithFlags(&hs1, cudaStreamNonBlocking);
        cudaStreamCreateWithFlags(&hs2, cudaStreamNonBlocking);
        cudaEventCreateWithFlags(&hevStart,  cudaEventDisableTiming);
        cudaEventCreateWithFlags(&hevGemm1,  cudaEventDisableTiming);
        cudaEventCreateWithFlags(&hevFillE,  cudaEventDisableTiming);
        cudaEventCreateWithFlags(&hevFillCN, cudaEventDisableTiming);
        cudaEventCreateWithFlags(&hevH,      cudaEventDisableTiming);
        cudaEventCreateWithFlags(&hevDinvp,  cudaEventDisableTiming);
        cudaEventCreateWithFlags(&hevZeroP,  cudaEventDisableTiming);
        cudaEventCreateWithFlags(&hevSide,   cudaEventDisableTiming);
    }
};
static StreamInit s_init_;
}

// ---------------- histograms ----------------
__global__ void k_histE(const int* __restrict__ dst, int E) {
    int i = blockIdx.x * blockDim.x + threadIdx.x;
    if (i < E) atomicAdd(&g_cntE[dst[i]], 1);
}
__global__ void k_histM(const int* __restrict__ cc, const int* __restrict__ cn, int M) {
    int i = blockIdx.x * blockDim.x + threadIdx.x;
    if (i < M) {
        atomicAdd(&g_cntC[cc[i]], 1);
        atomicAdd(&g_cntN[cn[i]], 1);
    }
}

// ---------------- generic 3-phase scan ----------------
__global__ __launch_bounds__(256)
void k_scanA1(const int* __restrict__ cnt, int n, int base) {
    int t = threadIdx.x;
    int off0 = blockIdx.x * SCAN_BS + t * 8;
    int s = 0;
    #pragma unroll
    for (int k = 0; k < 8; k++) {
        int idx = off0 + k;
        if (idx < n) s += cnt[idx];
    }
    __shared__ int red[256];
    red[t] = s;
    __syncthreads();
    #pragma unroll
    for (int d = 128; d > 0; d >>= 1) {
        if (t < d) red[t] += red[t + d];
        __syncthreads();
    }
    if (t == 0) g_blockSums[base + blockIdx.x] = red[0];
}

__global__ void k_scanB1(int nb, int base, int* __restrict__ totalOut) {
    if (threadIdx.x == 0) {
        int run = 0;
        for (int i = 0; i < nb; i++) {
            int v = g_blockSums[base + i];
            g_blockOffs[base + i] = run;
            run += v;
        }
        *totalOut = run;
    }
}

__global__ __launch_bounds__(256)
void k_scanC1(const int* __restrict__ cnt, int* __restrict__ off, int* __restrict__ cur,
              int n, int base) {
    int t = threadIdx.x;
    int off0 = blockIdx.x * SCAN_BS + t * 8;
    int v[8];
    int s = 0;
    #pragma unroll
    for (int k = 0; k < 8; k++) {
        int idx = off0 + k;
        v[k] = (idx < n) ? cnt[idx] : 0;
        s += v[k];
    }
    __shared__ int red[256];
    red[t] = s;
    __syncthreads();
    #pragma unroll
    for (int d = 1; d < 256; d <<= 1) {
        int x = (t >= d) ? red[t - d] : 0;
        __syncthreads();
        red[t] += x;
        __syncthreads();
    }
    int pre = g_blockOffs[base + blockIdx.x] + red[t] - s;
    #pragma unroll
    for (int k = 0; k < 8; k++) {
        int idx = off0 + k;
        if (idx < n) { off[idx] = pre; cur[idx] = pre; }
        pre += v[k];
    }
}

// ---------------- CSR fills ----------------
__global__ void k_fillE(const int* __restrict__ src, const int* __restrict__ dst,
                        const float* __restrict__ w, int E) {
    int i = blockIdx.x * blockDim.x + threadIdx.x;
    if (i >= E) return;
    int d = dst[i];
    float wv = w[i];
    int pos = atomicAdd(&g_curE[d], 1);
    g_edges[pos] = make_int2(src[i], __float_as_int(wv));
    atomicAdd(&g_deg[d], wv);
}
__global__ void k_fillCN(const int* __restrict__ cn, const int* __restrict__ cc, int M) {
    int i = blockIdx.x * blockDim.x + threadIdx.x;
    if (i >= M) return;
    int node = cn[i], cl = cc[i];
    int pc = atomicAdd(&g_curC[cl], 1);
    g_cnC[pc] = node;
    int pn = atomicAdd(&g_curN[node], 1);
    g_ccN[pn] = cl;
}

__global__ void k_dinv(int N) {
    int i = blockIdx.x * blockDim.x + threadIdx.x;
    if (i < N) g_dinv[i] = rsqrtf(g_deg[i] + 1.0f);
}

// ---------------- fp16 helpers ----------------
__device__ __forceinline__ uint2 pack_half4(float4 v) {
    __half2 h0 = __floats2half2_rn(v.x, v.y);
    __half2 h1 = __floats2half2_rn(v.z, v.w);
    uint2 u;
    u.x = *(uint32_t*)&h0;
    u.y = *(uint32_t*)&h1;
    return u;
}

// ---------------- GCN pass 1 gather (fp16 rows, HFMA2 accumulation) ----------------
__global__ void gather_gcn1(const float* __restrict__ b_in, int N) {
    int wid = (blockIdx.x * blockDim.x + threadIdx.x) >> 5;
    if (wid >= N) return;
    int lane = threadIdx.x & 31;
    int beg = __ldg(&g_offE[wid]), end = __ldg(&g_offE[wid + 1]);
    float dn = __ldg(&g_dinv[wid]);
    __half2 acc0 = __float2half2_rn(0.f);
    __half2 acc1 = __float2half2_rn(0.f);
    int e = beg;
    for (; e + 8 <= end; e += 8) {
        int2 ed[8];
        #pragma unroll
        for (int q = 0; q < 8; q++) ed[q] = __ldg(&g_edges[e + q]);
        uint2 u[8];
        #pragma unroll
        for (int q = 0; q < 8; q++)
            u[q] = __ldg((const uint2*)(g_xwh + (size_t)ed[q].x * CH) + lane);
        #pragma unroll
        for (int q = 0; q < 8; q++) {
            float c = __int_as_float(ed[q].y) * dn * __ldg(&g_dinv[ed[q].x]);
            __half2 ch = __float2half2_rn(c);
            acc0 = __hfma2(ch, *(__half2*)&u[q].x, acc0);
            acc1 = __hfma2(ch, *(__half2*)&u[q].y, acc1);
        }
    }
    for (; e < end; e++) {
        int2 e0 = __ldg(&g_edges[e]);
        float c0 = __int_as_float(e0.y) * dn * __ldg(&g_dinv[e0.x]);
        uint2 u0 = __ldg((const uint2*)(g_xwh + (size_t)e0.x * CH) + lane);
        __half2 ch = __float2half2_rn(c0);
        acc0 = __hfma2(ch, *(__half2*)&u0.x, acc0);
        acc1 = __hfma2(ch, *(__half2*)&u0.y, acc1);
    }
    float2 a0 = __half22float2(acc0);
    float2 a1 = __half22float2(acc1);
    float4 acc = make_float4(a0.x, a0.y, a1.x, a1.y);
    uint2 us = __ldg((const uint2*)(g_xwh + (size_t)wid * CH) + lane);
    float2 s0 = __half22float2(*(__half2*)&us.x);
    float2 s1 = __half22float2(*(__half2*)&us.y);
    float4 bv = __ldg((const float4*)b_in + lane);
    float dd = dn * dn;
    acc.x = fmaxf(fmaf(dd, s0.x, acc.x) + bv.x, 0.f);
    acc.y = fmaxf(fmaf(dd, s0.y, acc.y) + bv.y, 0.f);
    acc.z = fmaxf(fmaf(dd, s1.x, acc.z) + bv.z, 0.f);
    acc.w = fmaxf(fmaf(dd, s1.y, acc.w) + bv.w, 0.f);
    *((uint2*)(g_hh + (size_t)wid * CH) + lane) = pack_half4(acc);
}

// ---------------- GCN pass 2 gather (fp16, HFMA2, covered-only) ----------------
__global__ void gather_ye(int N) {
    int wid = (blockIdx.x * blockDim.x + threadIdx.x) >> 5;
    if (wid >= N) return;
    if (__ldg(&g_offN[wid]) == __ldg(&g_offN[wid + 1])) return;
    int lane = threadIdx.x & 31;
    int beg = __ldg(&g_offE[wid]), end = __ldg(&g_offE[wid + 1]);
    __half2 acc0 = __float2half2_rn(0.f);
    __half2 acc1 = __float2half2_rn(0.f);
    int e = beg;
    for (; e + 8 <= end; e += 8) {
        int2 ed[8];
        #pragma unroll
        for (int q = 0; q < 8; q++) ed[q] = __ldg(&g_edges[e + q]);
        uint2 u[8];
        #pragma unroll
        for (int q = 0; q < 8; q++)
            u[q] = __ldg((const uint2*)(g_znh + (size_t)ed[q].x * CH) + lane);
        #pragma unroll
        for (int q = 0; q < 8; q++) {
            __half2 ch = __float2half2_rn(__int_as_float(ed[q].y));
            acc0 = __hfma2(ch, *(__half2*)&u[q].x, acc0);
            acc1 = __hfma2(ch, *(__half2*)&u[q].y, acc1);
        }
    }
    for (; e < end; e++) {
        int2 e0 = __ldg(&g_edges[e]);
        uint2 u0 = __ldg((const uint2*)(g_znh + (size_t)e0.x * CH) + lane);
        __half2 ch = __float2half2_rn(__int_as_float(e0.y));
        acc0 = __hfma2(ch, *(__half2*)&u0.x, acc0);
        acc1 = __hfma2(ch, *(__half2*)&u0.y, acc1);
    }
    uint2 outv;
    outv.x = *(uint32_t*)&acc0;
    outv.y = *(uint32_t*)&acc1;
    *((uint2*)(g_yeh + (size_t)wid * CH) + lane) = outv;
}

// ---------------- cover pooling gather (half2 add/max) ----------------
__global__ void gather_xp(int KC) {
    int wid = (blockIdx.x * blockDim.x + threadIdx.x) >> 5;
    if (wid >= KC) return;
    int lane = threadIdx.x & 31;
    int beg = __ldg(&g_offC[wid]), end = __ldg(&g_offC[wid + 1]);
    __half2 add0 = __float2half2_rn(0.f);
    __half2 add1 = __float2half2_rn(0.f);
    __half2 mx0  = __float2half2_rn(0.f);   // h >= 0 post-relu
    __half2 mx1  = __float2half2_rn(0.f);
    for (int j = beg; j < end; j++) {
        int node = __ldg(&g_cnC[j]);
        uint2 u = __ldg((const uint2*)(g_hh + (size_t)node * CH) + lane);
        __half2 v0 = *(__half2*)&u.x;
        __half2 v1 = *(__half2*)&u.y;
        add0 = __hadd2(add0, v0);
        add1 = __hadd2(add1, v1);
        mx0 = __hmax2(mx0, v0);
        mx1 = __hmax2(mx1, v1);
    }
    __half* xp = g_xph + (size_t)wid * (2 * CH);
    uint2 ua, um;
    ua.x = *(uint32_t*)&add0; ua.y = *(uint32_t*)&add1;
    um.x = *(uint32_t*)&mx0;  um.y = *(uint32_t*)&mx1;
    *((uint2*)xp + lane) = ua;
    *((uint2*)(xp + CH) + lane) = um;
}

// ---------------- zn = C xws gather (half2 add) ----------------
__global__ void gather_zn(int N) {
    int wid = (blockIdx.x * blockDim.x + threadIdx.x) >> 5;
    if (wid >= N) return;
    int lane = threadIdx.x & 31;
    int beg = __ldg(&g_offN[wid]), end = __ldg(&g_offN[wid + 1]);
    __half2 acc0 = __float2half2_rn(0.f);
    __half2 acc1 = __float2half2_rn(0.f);
    for (int j = beg; j < end; j++) {
        int cl = __ldg(&g_ccN[j]);
        uint2 u = __ldg((const uint2*)(g_xwsh + (size_t)cl * CH) + lane);
        acc0 = __hadd2(acc0, *(__half2*)&u.x);
        acc1 = __hadd2(acc1, *(__half2*)&u.y);
    }
    uint2 outv;
    outv.x = *(uint32_t*)&acc0;
    outv.y = *(uint32_t*)&acc1;
    *((uint2*)(g_znh + (size_t)wid * CH) + lane) = outv;
}

// ---------------- hp gather (half2 sum, fp32 epilogue, fp16 out) ----------------
__global__ void gather_hp(const float* __restrict__ b_blk, int KC) {
    int wid = (blockIdx.x * blockDim.x + threadIdx.x) >> 5;
    if (wid >= KC) return;
    int lane = threadIdx.x & 31;
    int beg = __ldg(&g_offC[wid]), end = __ldg(&g_offC[wid + 1]);
    __half2 acc0 = __float2half2_rn(0.f);
    __half2 acc1 = __float2half2_rn(0.f);
    for (int j = beg; j < end; j++) {
        int node = __ldg(&g_cnC[j]);
        uint2 u = __ldg((const uint2*)(g_yeh + (size_t)node * CH) + lane);
        acc0 = __hadd2(acc0, *(__half2*)&u.x);
        acc1 = __hadd2(acc1, *(__half2*)&u.y);
    }
    float2 a0 = __half22float2(acc0);
    float2 a1 = __half22float2(acc1);
    float4 acc = make_float4(a0.x, a0.y, a1.x, a1.y);
    float dp = __ldg(&g_dinvp[wid]);
    uint2 ux = __ldg((const uint2*)(g_xwsh + (size_t)wid * CH) + lane);
    float2 x0 = __half22float2(*(__half2*)&ux.x);
    float2 x1 = __half22float2(*(__half2*)&ux.y);
    float4 bv = __ldg((const float4*)b_blk + lane);
    acc.x = fmaxf(fmaf(dp, acc.x + x0.x, bv.x), 0.f);
    acc.y = fmaxf(fmaf(dp, acc.y + x0.y, bv.y), 0.f);
    acc.z = fmaxf(fmaf(dp, acc.z + x1.x, bv.z), 0.f);
    acc.w = fmaxf(fmaf(dp, acc.w + x1.y, bv.w), 0.f);
    *((uint2*)(g_hph + (size_t)wid * CH) + lane) = pack_half4(acc);
}

// ---------------- aprime(ones) scalar chain ----------------
__global__ void k_ye1g(int N) {
    int n = blockIdx.x * blockDim.x + threadIdx.x;
    if (n >= N) return;
    int beg = g_offE[n], end = g_offE[n + 1];
    float s = 0.f;
    for (int e = beg; e < end; e++) {
        int2 ed = __ldg(&g_edges[e]);
        s += __int_as_float(ed.y) * (float)__ldg(&g_cntN[ed.x]);
    }
    g_ye1[n] = s;
}
__global__ void k_dinvp_g(int KC) {
    int c = blockIdx.x * blockDim.x + threadIdx.x;
    if (c >= KC) return;
    int beg = g_offC[c], end = g_offC[c + 1];
    float s = 0.f;
    for (int j = beg; j < end; j++) s += __ldg(&g_ye1[g_cnC[j]]);
    g_dinvp[c] = rsqrtf(s + 1.0f);
}

// ---------------- sorted-label segment sum+max pooling (fp16 input) ----------------
__global__ void pool_sorted_h(const __half* __restrict__ V, const int* __restrict__ lab,
                              float* __restrict__ S, float* __restrict__ X, int R, int chunk) {
    int t = threadIdx.x;
    long start = (long)blockIdx.x * chunk;
    if (start >= R) return;
    long end = start + chunk; if (end > R) end = R;
    int cur = __ldg(lab + start);
    float s = 0.f, m = 0.f;
    for (long r = start; r < end; r++) {
        int l = __ldg(lab + r);
        if (l != cur) {
            atomicAdd(&S[(size_t)cur * CH + t], s);
            atomicMax((unsigned int*)&X[(size_t)cur * CH + t], __float_as_uint(m));
            s = 0.f; m = 0.f; cur = l;
        }
        float v = __half2float(__ldg(V + (size_t)r * CH + t));
        s += v; m = fmaxf(m, v);
    }
    atomicAdd(&S[(size_t)cur * CH + t], s);
    atomicMax((unsigned int*)&X[(size_t)cur * CH + t], __float_as_uint(m));
}

// ---------------- cluster-batch counts via binary search ----------------
__global__ void k_ccounts_bs(const int* __restrict__ cb, int KC) {
    int b = threadIdx.x;
    if (b >= CB) return;
    int lo0 = 0, hi0 = KC;
    while (lo0 < hi0) { int mid = (lo0 + hi0) >> 1; if (__ldg(cb + mid) < b) lo0 = mid + 1; else hi0 = mid; }
    int lo1 = lo0, hi1 = KC;
    while (lo1 < hi1) { int mid = (lo1 + hi1) >> 1; if (__ldg(cb + mid) < b + 1) lo1 = mid + 1; else hi1 = mid; }
    g_cc[b] = (float)(lo1 - lo0);
}

// ================= 1xTF32 tensor-core GEMM (fp32/fp16 A, fp32/fp16 out) =================
#define SMS 136

__device__ __forceinline__ uint32_t f2tf32(float f) {
    uint32_t u;
    asm("cvt.rna.tf32.f32 %0, %1;" : "=r"(u) : "f"(f));
    return u;
}
__device__ __forceinline__ void mma_tf32(float c[4], uint32_t a0, uint32_t a1,
                                         uint32_t a2, uint32_t a3,
                                         uint32_t b0, uint32_t b1) {
    asm volatile(
        "mma.sync.aligned.m16n8k8.row.col.f32.tf32.tf32.f32 "
        "{%0,%1,%2,%3}, {%4,%5,%6,%7}, {%8,%9}, {%0,%1,%2,%3};"
        : "+f"(c[0]), "+f"(c[1]), "+f"(c[2]), "+f"(c[3])
        : "r"(a0), "r"(a1), "r"(a2), "r"(a3), "r"(b0), "r"(b1));
}

__global__ __launch_bounds__(256)
void gemm_tf32(const float* __restrict__ A, const __half* __restrict__ Ah,
               const float* __restrict__ B,
               float* __restrict__ C, __half* __restrict__ Ch,
               int M, int K, const float* __restrict__ rowscale) {
    __shared__ float As[32 * SMS];
    __shared__ float Bs[32 * SMS];
    int tid = threadIdx.x;
    int lane = tid & 31;
    int wid = tid >> 5;
    int wm = wid & 1;
    int wn = wid >> 1;
    int lr = lane >> 2;
    int lc = lane & 3;
    int rowBase = blockIdx.x * 128;

    float acc[4][4][4];
    #pragma unroll
    for (int i = 0; i < 4; i++)
        #pragma unroll
        for (int j = 0; j < 4; j++)
            #pragma unroll
            for (int r = 0; r < 4; r++) acc[i][j][r] = 0.f;

    int aRow = tid >> 3;
    int aK4  = (tid & 7) * 4;
    int bK   = tid >> 5;
    int bN4  = lane * 4;

    for (int kc = 0; kc < K; kc += 32) {
        #pragma unroll
        for (int p = 0; p < 4; p++) {
            int m = p * 32 + aRow;
            int gr = rowBase + m;
            float4 av = make_float4(0.f, 0.f, 0.f, 0.f);
            if (gr < M) {
                if (Ah) {
                    uint2 u = *(const uint2*)(Ah + (size_t)gr * K + kc + aK4);
                    float2 f0 = __half22float2(*(__half2*)&u.x);
                    float2 f1 = __half22float2(*(__half2*)&u.y);
                    av = make_float4(f0.x, f0.y, f1.x, f1.y);
                } else {
                    av = *(const float4*)(A + (size_t)gr * K + kc + aK4);
                }
            }
            As[(aK4 + 0) * SMS + m] = av.x;
            As[(aK4 + 1) * SMS + m] = av.y;
            As[(aK4 + 2) * SMS + m] = av.z;
            As[(aK4 + 3) * SMS + m] = av.w;
        }
        #pragma unroll
        for (int p = 0; p < 4; p++) {
            int k = p * 8 + bK;
            float4 bv = *(const float4*)(B + (size_t)(kc + k) * 128 + bN4);
            *(float4*)&Bs[k * SMS + bN4] = bv;
        }
        __syncthreads();

        #pragma unroll
        for (int ks = 0; ks < 4; ks++) {
            int k0 = ks * 8;
            uint32_t a[4][4];
            #pragma unroll
            for (int mi = 0; mi < 4; mi++) {
                int mb = wm * 64 + mi * 16;
                a[mi][0] = f2tf32(As[(k0 + lc) * SMS + mb + lr]);
                a[mi][1] = f2tf32(As[(k0 + lc) * SMS + mb + lr + 8]);
                a[mi][2] = f2tf32(As[(k0 + 4 + lc) * SMS + mb + lr]);
                a[mi][3] = f2tf32(As[(k0 + 4 + lc) * SMS + mb + lr + 8]);
            }
            uint32_t b[4][2];
            #pragma unroll
            for (int ni = 0; ni < 4; ni++) {
                int nb = wn * 32 + ni * 8;
                b[ni][0] = f2tf32(Bs[(k0 + lc) * SMS + nb + lr]);
                b[ni][1] = f2tf32(Bs[(k0 + 4 + lc) * SMS + nb + lr]);
            }
            #pragma unroll
            for (int mi = 0; mi < 4; mi++)
                #pragma unroll
                for (int ni = 0; ni < 4; ni++)
                    mma_tf32(acc[mi][ni], a[mi][0], a[mi][1], a[mi][2], a[mi][3],
                             b[ni][0], b[ni][1]);
        }
        __syncthreads();
    }

    #pragma unroll
    for (int mi = 0; mi < 4; mi++) {
        int r0 = rowBase + wm * 64 + mi * 16 + lr;
        int r1 = r0 + 8;
        float s0 = 1.f, s1 = 1.f;
        if (rowscale) {
            if (r0 < M) s0 = __ldg(rowscale + r0);
            if (r1 < M) s1 = __ldg(rowscale + r1);
        }
        #pragma unroll
        for (int ni = 0; ni < 4; ni++) {
            int col = wn * 32 + ni * 8 + lc * 2;
            if (Ch) {
                if (r0 < M) {
                    __half2 hv = __floats2half2_rn(acc[mi][ni][0] * s0, acc[mi][ni][1] * s0);
                    *(__half2*)(Ch + (size_t)r0 * 128 + col) = hv;
                }
                if (r1 < M) {
                    __half2 hv = __floats2half2_rn(acc[mi][ni][2] * s1, acc[mi][ni][3] * s1);
                    *(__half2*)(Ch + (size_t)r1 * 128 + col) = hv;
                }
            } else {
                if (r0 < M) {
                    float2 v = make_float2(acc[mi][ni][0] * s0, acc[mi][ni][1] * s0);
                    *(float2*)(C + (size_t)r0 * 128 + col) = v;
                }
                if (r1 < M) {
                    float2 v = make_float2(acc[mi][ni][2] * s1, acc[mi][ni][3] * s1);
                    *(float2*)(C + (size_t)r1 * 128 + col) = v;
                }
            }
        }
    }
}

// ---------------- final BN + MLP + softmax ----------------
__global__ void k_mlp(const float* __restrict__ gamma, const float* __restrict__ beta,
                      const float* __restrict__ mu, const float* __restrict__ var,
                      const float* __restrict__ W1, const float* __restrict__ b1,
                      const float* __restrict__ W2, const float* __restrict__ b2,
                      float* __restrict__ out) {
    __shared__ float zs[4 * CH];
    __shared__ float y1s[CH];
    __shared__ float lg[CCOUT];
    int b = blockIdx.x, t = threadIdx.x;
    float inv_cc = 1.0f / g_cc[b];
    float raws[4];
    raws[0] = g_Sh [b * CH + t];
    raws[1] = g_Xh [b * CH + t];
    raws[2] = g_Shp[b * CH + t] * inv_cc;
    raws[3] = g_Xhp[b * CH + t];
    #pragma unroll
    for (int seg = 0; seg < 4; seg++) {
        int idx = seg * CH + t;
        zs[idx] = (raws[seg] - mu[idx]) * rsqrtf(var[idx] + 1e-5f) * gamma[idx] + beta[idx];
    }
    __syncthreads();
    float acc = b1[t];
    for (int k = 0; k < 4 * CH; k++) acc += zs[k] * W1[(size_t)k * CH + t];
    y1s[t] = fmaxf(acc, 0.f);
    __syncthreads();
    if (t < CCOUT) {
        float a = b2[t];
        for (int j = 0; j < CH; j++) a += y1s[j] * W2[j * CCOUT + t];
        lg[t] = a;
    }
    __syncthreads();
    if (t == 0) {
        float mx = lg[0];
        for (int c = 1; c < CCOUT; c++) mx = fmaxf(mx, lg[c]);
        float e[CCOUT]; float sum = 0.f;
        for (int c = 0; c < CCOUT; c++) { e[c] = expf(lg[c] - mx); sum += e[c]; }
        for (int c = 0; c < CCOUT; c++) out[b * CCOUT + c] = e[c] / sum;
    }
}

// ---------------- host ----------------
extern "C" void kernel_launch(void* const* d_in, const int* in_sizes, int n_in,
                              void* d_out, int out_size) {
    const float* x     = (const float*)d_in[0];
    const int*   ei    = (const int*)  d_in[1];
    const float* w     = (const float*)d_in[2];
    const int*   batch = (const int*)  d_in[3];
    const int*   cn    = (const int*)  d_in[4];
    const int*   cc    = (const int*)  d_in[5];
    const int*   cb    = (const int*)  d_in[6];
    const float* W_in  = (const float*)d_in[7];
    const float* b_in  = (const float*)d_in[8];
    const float* W_blk = (const float*)d_in[9];
    const float* b_blk = (const float*)d_in[10];
    const float* gam   = (const float*)d_in[11];
    const float* bet   = (const float*)d_in[12];
    const float* mu    = (const float*)d_in[13];
    const float* var   = (const float*)d_in[14];
    const float* W1    = (const float*)d_in[15];
    const float* b1    = (const float*)d_in[16];
    const float* W2    = (const float*)d_in[17];
    const float* b2    = (const float*)d_in[18];
    float* out = (float*)d_out;

    int E  = in_sizes[2];
    int N  = in_sizes[3];
    int M  = in_sizes[4];
    int KC = in_sizes[6];
    const int* src = ei;
    const int* dst = ei + E;

    float *p_Sh, *p_Xh, *p_Shp, *p_Xhp, *p_dinvp, *p_deg;
    __half *p_xwh, *p_hh, *p_xph, *p_xwsh, *p_hph;
    int *p_cntE, *p_cntC, *p_cntN, *p_offE, *p_offC, *p_offN, *p_curE, *p_curC, *p_curN;
    cudaGetSymbolAddress((void**)&p_xwh,  g_xwh);
    cudaGetSymbolAddress((void**)&p_hh,   g_hh);
    cudaGetSymbolAddress((void**)&p_xph,  g_xph);
    cudaGetSymbolAddress((void**)&p_xwsh, g_xwsh);
    cudaGetSymbolAddress((void**)&p_hph,  g_hph);
    cudaGetSymbolAddress((void**)&p_Sh,   g_Sh);
    cudaGetSymbolAddress((void**)&p_Xh,   g_Xh);
    cudaGetSymbolAddress((void**)&p_Shp,  g_Shp);
    cudaGetSymbolAddress((void**)&p_Xhp,  g_Xhp);
    cudaGetSymbolAddress((void**)&p_dinvp, g_dinvp);
    cudaGetSymbolAddress((void**)&p_deg,  g_deg);
    cudaGetSymbolAddress((void**)&p_cntE, g_cntE);
    cudaGetSymbolAddress((void**)&p_cntC, g_cntC);
    cudaGetSymbolAddress((void**)&p_cntN, g_cntN);
    cudaGetSymbolAddress((void**)&p_offE, g_offE);
    cudaGetSymbolAddress((void**)&p_offC, g_offC);
    cudaGetSymbolAddress((void**)&p_offN, g_offN);
    cudaGetSymbolAddress((void**)&p_curE, g_curE);
    cudaGetSymbolAddress((void**)&p_curC, g_curC);
    cudaGetSymbolAddress((void**)&p_curN, g_curN);

    const int T = 256;
    int warpsN  = (int)(((long)N * 32 + T - 1) / T);
    int warpsKC = (int)(((long)KC * 32 + T - 1) / T);
    int bE = (N + SCAN_BS - 1) / SCAN_BS;
    int bC = (KC + SCAN_BS - 1) / SCAN_BS;
    int bN = (N + SCAN_BS - 1) / SCAN_BS;

    // ---- fork ----
    cudaEventRecord(hevStart, 0);

    // ===== s1: gemm1 (fp16 output), then aprime(ones) chain =====
    cudaStreamWaitEvent(hs1, hevStart, 0);
    gemm_tf32<<<(N + 127) / 128, 256, 0, hs1>>>(x, nullptr, W_in, nullptr, p_xwh, N, CH, nullptr);
    cudaEventRecord(hevGemm1, hs1);

    // ===== s2: C/N-side CSR build + pooling zeroing + ccounts =====
    cudaStreamWaitEvent(hs2, hevStart, 0);
    cudaMemsetAsync(p_cntC, 0, (size_t)KC * 4, hs2);
    cudaMemsetAsync(p_cntN, 0, (size_t)N * 4, hs2);
    cudaMemsetAsync(p_Sh,   0, (size_t)CB * CH * 4, hs2);
    cudaMemsetAsync(p_Xh,   0, (size_t)CB * CH * 4, hs2);
    cudaMemsetAsync(p_Shp,  0, (size_t)CB * CH * 4, hs2);
    cudaMemsetAsync(p_Xhp,  0, (size_t)CB * CH * 4, hs2);
    cudaEventRecord(hevZeroP, hs2);
    k_ccounts_bs<<<1, CB, 0, hs2>>>(cb, KC);
    k_histM<<<(M + T - 1) / T, T, 0, hs2>>>(cc, cn, M);
    k_scanA1<<<bC, 256, 0, hs2>>>(p_cntC, KC, 64);
    k_scanB1<<<1, 32, 0, hs2>>>(bC, 64, p_offC + KC);
    k_scanC1<<<bC, 256, 0, hs2>>>(p_cntC, p_offC, p_curC, KC, 64);
    k_scanA1<<<bN, 256, 0, hs2>>>(p_cntN, N, 128);
    k_scanB1<<<1, 32, 0, hs2>>>(bN, 128, p_offN + N);
    k_scanC1<<<bN, 256, 0, hs2>>>(p_cntN, p_offN, p_curN, N, 128);
    k_fillCN<<<(M + T - 1) / T, T, 0, hs2>>>(cn, cc, M);
    cudaEventRecord(hevFillCN, hs2);

    // ===== s0: E-side CSR build =====
    cudaMemsetAsync(p_cntE, 0, (size_t)N * 4, 0);
    cudaMemsetAsync(p_deg,  0, (size_t)N * 4, 0);
    k_histE<<<(E + T - 1) / T, T>>>(dst, E);
    k_scanA1<<<bE, 256>>>(p_cntE, N, 0);
    k_scanB1<<<1, 32>>>(bE, 0, p_offE + N);
    k_scanC1<<<bE, 256>>>(p_cntE, p_offE, p_curE, N, 0);
    k_fillE<<<(E + T - 1) / T, T>>>(src, dst, w, E);
    cudaEventRecord(hevFillE, 0);
    k_dinv<<<(N + T - 1) / T, T>>>(N);

    // s1: aprime(ones) chain (needs CSR-E + cntN/CSR-C)
    cudaStreamWaitEvent(hs1, hevFillE, 0);
    cudaStreamWaitEvent(hs1, hevFillCN, 0);
    k_ye1g   <<<(N + T - 1) / T, T, 0, hs1>>>(N);
    k_dinvp_g<<<(KC + T - 1) / T, T, 0, hs1>>>(KC);
    cudaEventRecord(hevDinvp, hs1);

    // s0: GCN pass 1 (needs xwh + CSR-E + dinv)
    cudaStreamWaitEvent(0, hevGemm1, 0);
    gather_gcn1<<<warpsN, T>>>(b_in, N);
    cudaEventRecord(hevH, 0);

    // s2: node pooling (after zeroing + ccounts on s2; needs hh)
    cudaStreamWaitEvent(hs2, hevH, 0);
    pool_sorted_h<<<(N + 127) / 128, CH, 0, hs2>>>(p_hh, batch, p_Sh, p_Xh, N, 128);
    cudaEventRecord(hevSide, hs2);

    // s0: cover pooling (fp16), gemm2 (fp16 A/out), aprime(xws) chain, hp (fp16), cluster pooling
    cudaStreamWaitEvent(0, hevFillCN, 0);
    gather_xp<<<warpsKC, T>>>(KC);
    cudaStreamWaitEvent(0, hevDinvp, 0);
    gemm_tf32<<<(KC + 127) / 128, 256>>>(nullptr, p_xph, W_blk, nullptr, p_xwsh, KC, 2 * CH, p_dinvp);
    gather_zn<<<warpsN, T>>>(N);
    gather_ye<<<warpsN, T>>>(N);
    gather_hp<<<warpsKC, T>>>(b_blk, KC);
    cudaStreamWaitEvent(0, hevZeroP, 0);
    pool_sorted_h<<<(KC + 127) / 128, CH>>>(p_hph, cb, p_Shp, p_Xhp, KC, 128);

    // ---- join + final ----
    cudaStreamWaitEvent(0, hevSide, 0);
    k_mlp<<<CB, CH>>>(gam, bet, mu, var, W1, b1, W2, b2, out);
}

// round 17
// speedup vs baseline: 1.0692x; 1.0311x over previous
#include <cuda_runtime.h>
#include <cuda_fp16.h>
#include <math.h>
#include <stdint.h>

// Problem constants (fixed by the dataset)
#define CN   100000
#define CE   1600000
#define CH   128
#define CM   150000
#define CKC  60000
#define CB   64
#define CCOUT 10

// ---------------- scratch (device globals; no allocation) ----------------
__device__ __align__(128) __half g_xwh [(size_t)CN * CH];    // fp16 x @ W_in
__device__ __align__(128) __half g_hh  [(size_t)CN * CH];    // fp16 relu(gcn1)
__device__ __align__(128) __half g_znh [(size_t)CN * CH];    // fp16 zn
__device__ __align__(128) __half g_yeh [(size_t)CN * CH];    // fp16 ye
__device__ __align__(128) __half g_xph [(size_t)CKC * 2 * CH]; // fp16 [add|max] cover pool
__device__ __align__(128) __half g_xwsh[(size_t)CKC * CH];   // fp16 dinvp*(xp@W_blk)
__device__ __align__(128) __half g_hph [(size_t)CKC * CH];   // fp16 hp
__device__ __align__(128) float g_deg  [CN];
__device__ __align__(128) float g_dinv [CN];
__device__ __align__(128) float g_ye1  [CN];
__device__ __align__(128) float g_dinvp[CKC];
__device__ __align__(128) float g_Sh [CB * CH];
__device__ __align__(128) float g_Xh [CB * CH];
__device__ __align__(128) float g_Shp[CB * CH];
__device__ __align__(128) float g_Xhp[CB * CH];
__device__ __align__(128) float g_cc [CB];

// CSR-E: dst -> (src, w)
__device__ __align__(128) int  g_cntE[CN];
__device__ __align__(128) int  g_offE[CN + 1];
__device__ __align__(128) int  g_curE[CN];
__device__ __align__(128) int2 g_edges[CE];
// CSR-C: cluster -> cover_node entries
__device__ __align__(128) int  g_cntC[CKC];
__device__ __align__(128) int  g_offC[CKC + 1];
__device__ __align__(128) int  g_curC[CKC];
__device__ __align__(128) int  g_cnC [CM];
// CSR-N: node -> cover_cluster entries
__device__ __align__(128) int  g_cntN[CN];
__device__ __align__(128) int  g_offN[CN + 1];
__device__ __align__(128) int  g_curN[CN];
__device__ __align__(128) int  g_ccN [CM];

// scan temporaries (bases: E=0, C=64, N=128; each needs <64 blocks)
__device__ int g_blockSums[256];
__device__ int g_blockOffs[256];

#define SCAN_BS 2048

// ---------------- process-lifetime streams/events ----------------
static cudaStream_t hs1, hs2;
static cudaEvent_t hevStart, hevGemm1, hevFillE, hevFillCN, hevH,
                   hevDinvp, hevZeroP, hevSide;
namespace {
struct StreamInit {
    StreamInit() {
        cudaStreamCreateWithFlags(&hs1, cudaStreamNonBlocking);
        cudaStreamCreateWithFlags(&hs2, cudaStreamNonBlocking);
        cudaEventCreateWithFlags(&hevStart,  cudaEventDisableTiming);
        cudaEventCreateWithFlags(&hevGemm1,  cudaEventDisableTiming);
        cudaEventCreateWithFlags(&hevFillE,  cudaEventDisableTiming);
        cudaEventCreateWithFlags(&hevFillCN, cudaEventDisableTiming);
        cudaEventCreateWithFlags(&hevH,      cudaEventDisableTiming);
        cudaEventCreateWithFlags(&hevDinvp,  cudaEventDisableTiming);
        cudaEventCreateWithFlags(&hevZeroP,  cudaEventDisableTiming);
        cudaEventCreateWithFlags(&hevSide,   cudaEventDisableTiming);
    }
};
static StreamInit s_init_;
}

// ---------------- histograms ----------------
__global__ void k_histE(const int* __restrict__ dst, int E) {
    int i = blockIdx.x * blockDim.x + threadIdx.x;
    if (i < E) atomicAdd(&g_cntE[dst[i]], 1);
}
__global__ void k_histM(const int* __restrict__ cc, const int* __restrict__ cn, int M) {
    int i = blockIdx.x * blockDim.x + threadIdx.x;
    if (i < M) {
        atomicAdd(&g_cntC[cc[i]], 1);
        atomicAdd(&g_cntN[cn[i]], 1);
    }
}

// ---------------- generic 3-phase scan ----------------
__global__ __launch_bounds__(256)
void k_scanA1(const int* __restrict__ cnt, int n, int base) {
    int t = threadIdx.x;
    int off0 = blockIdx.x * SCAN_BS + t * 8;
    int s = 0;
    #pragma unroll
    for (int k = 0; k < 8; k++) {
        int idx = off0 + k;
        if (idx < n) s += cnt[idx];
    }
    __shared__ int red[256];
    red[t] = s;
    __syncthreads();
    #pragma unroll
    for (int d = 128; d > 0; d >>= 1) {
        if (t < d) red[t] += red[t + d];
        __syncthreads();
    }
    if (t == 0) g_blockSums[base + blockIdx.x] = red[0];
}

__global__ void k_scanB1(int nb, int base, int* __restrict__ totalOut) {
    if (threadIdx.x == 0) {
        int run = 0;
        for (int i = 0; i < nb; i++) {
            int v = g_blockSums[base + i];
            g_blockOffs[base + i] = run;
            run += v;
        }
        *totalOut = run;
    }
}

__global__ __launch_bounds__(256)
void k_scanC1(const int* __restrict__ cnt, int* __restrict__ off, int* __restrict__ cur,
              int n, int base) {
    int t = threadIdx.x;
    int off0 = blockIdx.x * SCAN_BS + t * 8;
    int v[8];
    int s = 0;
    #pragma unroll
    for (int k = 0; k < 8; k++) {
        int idx = off0 + k;
        v[k] = (idx < n) ? cnt[idx] : 0;
        s += v[k];
    }
    __shared__ int red[256];
    red[t] = s;
    __syncthreads();
    #pragma unroll
    for (int d = 1; d < 256; d <<= 1) {
        int x = (t >= d) ? red[t - d] : 0;
        __syncthreads();
        red[t] += x;
        __syncthreads();
    }
    int pre = g_blockOffs[base + blockIdx.x] + red[t] - s;
    #pragma unroll
    for (int k = 0; k < 8; k++) {
        int idx = off0 + k;
        if (idx < n) { off[idx] = pre; cur[idx] = pre; }
        pre += v[k];
    }
}

// ---------------- CSR fills ----------------
__global__ void k_fillE(const int* __restrict__ src, const int* __restrict__ dst,
                        const float* __restrict__ w, int E) {
    int i = blockIdx.x * blockDim.x + threadIdx.x;
    if (i >= E) return;
    int d = dst[i];
    float wv = w[i];
    int pos = atomicAdd(&g_curE[d], 1);
    g_edges[pos] = make_int2(src[i], __float_as_int(wv));
    atomicAdd(&g_deg[d], wv);
}
__global__ void k_fillCN(const int* __restrict__ cn, const int* __restrict__ cc, int M) {
    int i = blockIdx.x * blockDim.x + threadIdx.x;
    if (i >= M) return;
    int node = cn[i], cl = cc[i];
    int pc = atomicAdd(&g_curC[cl], 1);
    g_cnC[pc] = node;
    int pn = atomicAdd(&g_curN[node], 1);
    g_ccN[pn] = cl;
}

__global__ void k_dinv(int N) {
    int i = blockIdx.x * blockDim.x + threadIdx.x;
    if (i < N) g_dinv[i] = rsqrtf(g_deg[i] + 1.0f);
}

// ---------------- fp16 helpers ----------------
__device__ __forceinline__ uint2 pack_half4(float4 v) {
    __half2 h0 = __floats2half2_rn(v.x, v.y);
    __half2 h1 = __floats2half2_rn(v.z, v.w);
    uint2 u;
    u.x = *(uint32_t*)&h0;
    u.y = *(uint32_t*)&h1;
    return u;
}

// ---------------- GCN pass 1 gather (fp16 rows, HFMA2, predicated tail) ----------------
__global__ void gather_gcn1(const float* __restrict__ b_in, int N) {
    int wid = (blockIdx.x * blockDim.x + threadIdx.x) >> 5;
    if (wid >= N) return;
    int lane = threadIdx.x & 31;
    int beg = __ldg(&g_offE[wid]), end = __ldg(&g_offE[wid + 1]);
    float dn = __ldg(&g_dinv[wid]);
    __half2 acc0 = __float2half2_rn(0.f);
    __half2 acc1 = __float2half2_rn(0.f);
    int e = beg;
    for (; e + 8 <= end; e += 8) {
        int2 ed[8];
        #pragma unroll
        for (int q = 0; q < 8; q++) ed[q] = __ldg(&g_edges[e + q]);
        uint2 u[8];
        #pragma unroll
        for (int q = 0; q < 8; q++)
            u[q] = __ldg((const uint2*)(g_xwh + (size_t)ed[q].x * CH) + lane);
        #pragma unroll
        for (int q = 0; q < 8; q++) {
            float c = __int_as_float(ed[q].y) * dn * __ldg(&g_dinv[ed[q].x]);
            __half2 ch = __float2half2_rn(c);
            acc0 = __hfma2(ch, *(__half2*)&u[q].x, acc0);
            acc1 = __hfma2(ch, *(__half2*)&u[q].y, acc1);
        }
    }
    // predicated final batch: inactive slots -> row 0 with weight 0 (contributes 0)
    if (e < end) {
        int r = end - e;
        int2 ed[8];
        #pragma unroll
        for (int q = 0; q < 8; q++)
            ed[q] = (q < r) ? __ldg(&g_edges[e + q]) : make_int2(0, 0);
        uint2 u[8];
        #pragma unroll
        for (int q = 0; q < 8; q++)
            u[q] = __ldg((const uint2*)(g_xwh + (size_t)ed[q].x * CH) + lane);
        #pragma unroll
        for (int q = 0; q < 8; q++) {
            float c = __int_as_float(ed[q].y) * dn * __ldg(&g_dinv[ed[q].x]);
            __half2 ch = __float2half2_rn(c);
            acc0 = __hfma2(ch, *(__half2*)&u[q].x, acc0);
            acc1 = __hfma2(ch, *(__half2*)&u[q].y, acc1);
        }
    }
    float2 a0 = __half22float2(acc0);
    float2 a1 = __half22float2(acc1);
    float4 acc = make_float4(a0.x, a0.y, a1.x, a1.y);
    uint2 us = __ldg((const uint2*)(g_xwh + (size_t)wid * CH) + lane);
    float2 s0 = __half22float2(*(__half2*)&us.x);
    float2 s1 = __half22float2(*(__half2*)&us.y);
    float4 bv = __ldg((const float4*)b_in + lane);
    float dd = dn * dn;
    acc.x = fmaxf(fmaf(dd, s0.x, acc.x) + bv.x, 0.f);
    acc.y = fmaxf(fmaf(dd, s0.y, acc.y) + bv.y, 0.f);
    acc.z = fmaxf(fmaf(dd, s1.x, acc.z) + bv.z, 0.f);
    acc.w = fmaxf(fmaf(dd, s1.y, acc.w) + bv.w, 0.f);
    *((uint2*)(g_hh + (size_t)wid * CH) + lane) = pack_half4(acc);
}

// ---------------- GCN pass 2 gather (fp16, HFMA2, covered-only, predicated tail) ----------------
__global__ void gather_ye(int N) {
    int wid = (blockIdx.x * blockDim.x + threadIdx.x) >> 5;
    if (wid >= N) return;
    if (__ldg(&g_offN[wid]) == __ldg(&g_offN[wid + 1])) return;
    int lane = threadIdx.x & 31;
    int beg = __ldg(&g_offE[wid]), end = __ldg(&g_offE[wid + 1]);
    __half2 acc0 = __float2half2_rn(0.f);
    __half2 acc1 = __float2half2_rn(0.f);
    int e = beg;
    for (; e + 8 <= end; e += 8) {
        int2 ed[8];
        #pragma unroll
        for (int q = 0; q < 8; q++) ed[q] = __ldg(&g_edges[e + q]);
        uint2 u[8];
        #pragma unroll
        for (int q = 0; q < 8; q++)
            u[q] = __ldg((const uint2*)(g_znh + (size_t)ed[q].x * CH) + lane);
        #pragma unroll
        for (int q = 0; q < 8; q++) {
            __half2 ch = __float2half2_rn(__int_as_float(ed[q].y));
            acc0 = __hfma2(ch, *(__half2*)&u[q].x, acc0);
            acc1 = __hfma2(ch, *(__half2*)&u[q].y, acc1);
        }
    }
    if (e < end) {
        int r = end - e;
        int2 ed[8];
        #pragma unroll
        for (int q = 0; q < 8; q++)
            ed[q] = (q < r) ? __ldg(&g_edges[e + q]) : make_int2(0, 0);
        uint2 u[8];
        #pragma unroll
        for (int q = 0; q < 8; q++)
            u[q] = __ldg((const uint2*)(g_znh + (size_t)ed[q].x * CH) + lane);
        #pragma unroll
        for (int q = 0; q < 8; q++) {
            __half2 ch = __float2half2_rn(__int_as_float(ed[q].y));
            acc0 = __hfma2(ch, *(__half2*)&u[q].x, acc0);
            acc1 = __hfma2(ch, *(__half2*)&u[q].y, acc1);
        }
    }
    uint2 outv;
    outv.x = *(uint32_t*)&acc0;
    outv.y = *(uint32_t*)&acc1;
    *((uint2*)(g_yeh + (size_t)wid * CH) + lane) = outv;
}

// ---------------- cover pooling gather (half2 add/max) ----------------
__global__ void gather_xp(int KC) {
    int wid = (blockIdx.x * blockDim.x + threadIdx.x) >> 5;
    if (wid >= KC) return;
    int lane = threadIdx.x & 31;
    int beg = __ldg(&g_offC[wid]), end = __ldg(&g_offC[wid + 1]);
    __half2 add0 = __float2half2_rn(0.f);
    __half2 add1 = __float2half2_rn(0.f);
    __half2 mx0  = __float2half2_rn(0.f);   // h >= 0 post-relu
    __half2 mx1  = __float2half2_rn(0.f);
    for (int j = beg; j < end; j++) {
        int node = __ldg(&g_cnC[j]);
        uint2 u = __ldg((const uint2*)(g_hh + (size_t)node * CH) + lane);
        __half2 v0 = *(__half2*)&u.x;
        __half2 v1 = *(__half2*)&u.y;
        add0 = __hadd2(add0, v0);
        add1 = __hadd2(add1, v1);
        mx0 = __hmax2(mx0, v0);
        mx1 = __hmax2(mx1, v1);
    }
    __half* xp = g_xph + (size_t)wid * (2 * CH);
    uint2 ua, um;
    ua.x = *(uint32_t*)&add0; ua.y = *(uint32_t*)&add1;
    um.x = *(uint32_t*)&mx0;  um.y = *(uint32_t*)&mx1;
    *((uint2*)xp + lane) = ua;
    *((uint2*)(xp + CH) + lane) = um;
}

// ---------------- zn = C xws gather (half2 add) ----------------
__global__ void gather_zn(int N) {
    int wid = (blockIdx.x * blockDim.x + threadIdx.x) >> 5;
    if (wid >= N) return;
    int lane = threadIdx.x & 31;
    int beg = __ldg(&g_offN[wid]), end = __ldg(&g_offN[wid + 1]);
    __half2 acc0 = __float2half2_rn(0.f);
    __half2 acc1 = __float2half2_rn(0.f);
    for (int j = beg; j < end; j++) {
        int cl = __ldg(&g_ccN[j]);
        uint2 u = __ldg((const uint2*)(g_xwsh + (size_t)cl * CH) + lane);
        acc0 = __hadd2(acc0, *(__half2*)&u.x);
        acc1 = __hadd2(acc1, *(__half2*)&u.y);
    }
    uint2 outv;
    outv.x = *(uint32_t*)&acc0;
    outv.y = *(uint32_t*)&acc1;
    *((uint2*)(g_znh + (size_t)wid * CH) + lane) = outv;
}

// ---------------- hp gather (half2 sum, fp32 epilogue, fp16 out) ----------------
__global__ void gather_hp(const float* __restrict__ b_blk, int KC) {
    int wid = (blockIdx.x * blockDim.x + threadIdx.x) >> 5;
    if (wid >= KC) return;
    int lane = threadIdx.x & 31;
    int beg = __ldg(&g_offC[wid]), end = __ldg(&g_offC[wid + 1]);
    __half2 acc0 = __float2half2_rn(0.f);
    __half2 acc1 = __float2half2_rn(0.f);
    for (int j = beg; j < end; j++) {
        int node = __ldg(&g_cnC[j]);
        uint2 u = __ldg((const uint2*)(g_yeh + (size_t)node * CH) + lane);
        acc0 = __hadd2(acc0, *(__half2*)&u.x);
        acc1 = __hadd2(acc1, *(__half2*)&u.y);
    }
    float2 a0 = __half22float2(acc0);
    float2 a1 = __half22float2(acc1);
    float4 acc = make_float4(a0.x, a0.y, a1.x, a1.y);
    float dp = __ldg(&g_dinvp[wid]);
    uint2 ux = __ldg((const uint2*)(g_xwsh + (size_t)wid * CH) + lane);
    float2 x0 = __half22float2(*(__half2*)&ux.x);
    float2 x1 = __half22float2(*(__half2*)&ux.y);
    float4 bv = __ldg((const float4*)b_blk + lane);
    acc.x = fmaxf(fmaf(dp, acc.x + x0.x, bv.x), 0.f);
    acc.y = fmaxf(fmaf(dp, acc.y + x0.y, bv.y), 0.f);
    acc.z = fmaxf(fmaf(dp, acc.z + x1.x, bv.z), 0.f);
    acc.w = fmaxf(fmaf(dp, acc.w + x1.y, bv.w), 0.f);
    *((uint2*)(g_hph + (size_t)wid * CH) + lane) = pack_half4(acc);
}

// ---------------- aprime(ones) scalar chain ----------------
__global__ void k_ye1g(int N) {
    int n = blockIdx.x * blockDim.x + threadIdx.x;
    if (n >= N) return;
    int beg = g_offE[n], end = g_offE[n + 1];
    float s = 0.f;
    for (int e = beg; e < end; e++) {
        int2 ed = __ldg(&g_edges[e]);
        s += __int_as_float(ed.y) * (float)__ldg(&g_cntN[ed.x]);
    }
    g_ye1[n] = s;
}
__global__ void k_dinvp_g(int KC) {
    int c = blockIdx.x * blockDim.x + threadIdx.x;
    if (c >= KC) return;
    int beg = g_offC[c], end = g_offC[c + 1];
    float s = 0.f;
    for (int j = beg; j < end; j++) s += __ldg(&g_ye1[g_cnC[j]]);
    g_dinvp[c] = rsqrtf(s + 1.0f);
}

// ---------------- sorted-label segment sum+max pooling (fp16 input) ----------------
__global__ void pool_sorted_h(const __half* __restrict__ V, const int* __restrict__ lab,
                              float* __restrict__ S, float* __restrict__ X, int R, int chunk) {
    int t = threadIdx.x;
    long start = (long)blockIdx.x * chunk;
    if (start >= R) return;
    long end = start + chunk; if (end > R) end = R;
    int cur = __ldg(lab + start);
    float s = 0.f, m = 0.f;
    for (long r = start; r < end; r++) {
        int l = __ldg(lab + r);
        if (l != cur) {
            atomicAdd(&S[(size_t)cur * CH + t], s);
            atomicMax((unsigned int*)&X[(size_t)cur * CH + t], __float_as_uint(m));
            s = 0.f; m = 0.f; cur = l;
        }
        float v = __half2float(__ldg(V + (size_t)r * CH + t));
        s += v; m = fmaxf(m, v);
    }
    atomicAdd(&S[(size_t)cur * CH + t], s);
    atomicMax((unsigned int*)&X[(size_t)cur * CH + t], __float_as_uint(m));
}

// ---------------- cluster-batch counts via binary search ----------------
__global__ void k_ccounts_bs(const int* __restrict__ cb, int KC) {
    int b = threadIdx.x;
    if (b >= CB) return;
    int lo0 = 0, hi0 = KC;
    while (lo0 < hi0) { int mid = (lo0 + hi0) >> 1; if (__ldg(cb + mid) < b) lo0 = mid + 1; else hi0 = mid; }
    int lo1 = lo0, hi1 = KC;
    while (lo1 < hi1) { int mid = (lo1 + hi1) >> 1; if (__ldg(cb + mid) < b + 1) lo1 = mid + 1; else hi1 = mid; }
    g_cc[b] = (float)(lo1 - lo0);
}

// ================= 1xTF32 tensor-core GEMM (fp32/fp16 A, fp32/fp16 out) =================
#define SMS 136

__device__ __forceinline__ uint32_t f2tf32(float f) {
    uint32_t u;
    asm("cvt.rna.tf32.f32 %0, %1;" : "=r"(u) : "f"(f));
    return u;
}
__device__ __forceinline__ void mma_tf32(float c[4], uint32_t a0, uint32_t a1,
                                         uint32_t a2, uint32_t a3,
                                         uint32_t b0, uint32_t b1) {
    asm volatile(
        "mma.sync.aligned.m16n8k8.row.col.f32.tf32.tf32.f32 "
        "{%0,%1,%2,%3}, {%4,%5,%6,%7}, {%8,%9}, {%0,%1,%2,%3};"
        : "+f"(c[0]), "+f"(c[1]), "+f"(c[2]), "+f"(c[3])
        : "r"(a0), "r"(a1), "r"(a2), "r"(a3), "r"(b0), "r"(b1));
}

__global__ __launch_bounds__(256)
void gemm_tf32(const float* __restrict__ A, const __half* __restrict__ Ah,
               const float* __restrict__ B,
               float* __restrict__ C, __half* __restrict__ Ch,
               int M, int K, const float* __restrict__ rowscale) {
    __shared__ float As[32 * SMS];
    __shared__ float Bs[32 * SMS];
    int tid = threadIdx.x;
    int lane = tid & 31;
    int wid = tid >> 5;
    int wm = wid & 1;
    int wn = wid >> 1;
    int lr = lane >> 2;
    int lc = lane & 3;
    int rowBase = blockIdx.x * 128;

    float acc[4][4][4];
    #pragma unroll
    for (int i = 0; i < 4; i++)
        #pragma unroll
        for (int j = 0; j < 4; j++)
            #pragma unroll
            for (int r = 0; r < 4; r++) acc[i][j][r] = 0.f;

    int aRow = tid >> 3;
    int aK4  = (tid & 7) * 4;
    int bK   = tid >> 5;
    int bN4  = lane * 4;

    for (int kc = 0; kc < K; kc += 32) {
        #pragma unroll
        for (int p = 0; p < 4; p++) {
            int m = p * 32 + aRow;
            int gr = rowBase + m;
            float4 av = make_float4(0.f, 0.f, 0.f, 0.f);
            if (gr < M) {
                if (Ah) {
                    uint2 u = *(const uint2*)(Ah + (size_t)gr * K + kc + aK4);
                    float2 f0 = __half22float2(*(__half2*)&u.x);
                    float2 f1 = __half22float2(*(__half2*)&u.y);
                    av = make_float4(f0.x, f0.y, f1.x, f1.y);
                } else {
                    av = *(const float4*)(A + (size_t)gr * K + kc + aK4);
                }
            }
            As[(aK4 + 0) * SMS + m] = av.x;
            As[(aK4 + 1) * SMS + m] = av.y;
            As[(aK4 + 2) * SMS + m] = av.z;
            As[(aK4 + 3) * SMS + m] = av.w;
        }
        #pragma unroll
        for (int p = 0; p < 4; p++) {
            int k = p * 8 + bK;
            float4 bv = *(const float4*)(B + (size_t)(kc + k) * 128 + bN4);
            *(float4*)&Bs[k * SMS + bN4] = bv;
        }
        __syncthreads();

        #pragma unroll
        for (int ks = 0; ks < 4; ks++) {
            int k0 = ks * 8;
            uint32_t a[4][4];
            #pragma unroll
            for (int mi = 0; mi < 4; mi++) {
                int mb = wm * 64 + mi * 16;
                a[mi][0] = f2tf32(As[(k0 + lc) * SMS + mb + lr]);
                a[mi][1] = f2tf32(As[(k0 + lc) * SMS + mb + lr + 8]);
                a[mi][2] = f2tf32(As[(k0 + 4 + lc) * SMS + mb + lr]);
                a[mi][3] = f2tf32(As[(k0 + 4 + lc) * SMS + mb + lr + 8]);
            }
            uint32_t b[4][2];
            #pragma unroll
            for (int ni = 0; ni < 4; ni++) {
                int nb = wn * 32 + ni * 8;
                b[ni][0] = f2tf32(Bs[(k0 + lc) * SMS + nb + lr]);
                b[ni][1] = f2tf32(Bs[(k0 + 4 + lc) * SMS + nb + lr]);
            }
            #pragma unroll
            for (int mi = 0; mi < 4; mi++)
                #pragma unroll
                for (int ni = 0; ni < 4; ni++)
                    mma_tf32(acc[mi][ni], a[mi][0], a[mi][1], a[mi][2], a[mi][3],
                             b[ni][0], b[ni][1]);
        }
        __syncthreads();
    }

    #pragma unroll
    for (int mi = 0; mi < 4; mi++) {
        int r0 = rowBase + wm * 64 + mi * 16 + lr;
        int r1 = r0 + 8;
        float s0 = 1.f, s1 = 1.f;
        if (rowscale) {
            if (r0 < M) s0 = __ldg(rowscale + r0);
            if (r1 < M) s1 = __ldg(rowscale + r1);
        }
        #pragma unroll
        for (int ni = 0; ni < 4; ni++) {
            int col = wn * 32 + ni * 8 + lc * 2;
            if (Ch) {
                if (r0 < M) {
                    __half2 hv = __floats2half2_rn(acc[mi][ni][0] * s0, acc[mi][ni][1] * s0);
                    *(__half2*)(Ch + (size_t)r0 * 128 + col) = hv;
                }
                if (r1 < M) {
                    __half2 hv = __floats2half2_rn(acc[mi][ni][2] * s1, acc[mi][ni][3] * s1);
                    *(__half2*)(Ch + (size_t)r1 * 128 + col) = hv;
                }
            } else {
                if (r0 < M) {
                    float2 v = make_float2(acc[mi][ni][0] * s0, acc[mi][ni][1] * s0);
                    *(float2*)(C + (size_t)r0 * 128 + col) = v;
                }
                if (r1 < M) {
                    float2 v = make_float2(acc[mi][ni][2] * s1, acc[mi][ni][3] * s1);
                    *(float2*)(C + (size_t)r1 * 128 + col) = v;
                }
            }
        }
    }
}

// ---------------- final BN + MLP + softmax ----------------
__global__ void k_mlp(const float* __restrict__ gamma, const float* __restrict__ beta,
                      const float* __restrict__ mu, const float* __restrict__ var,
                      const float* __restrict__ W1, const float* __restrict__ b1,
                      const float* __restrict__ W2, const float* __restrict__ b2,
                      float* __restrict__ out) {
    __shared__ float zs[4 * CH];
    __shared__ float y1s[CH];
    __shared__ float lg[CCOUT];
    int b = blockIdx.x, t = threadIdx.x;
    float inv_cc = 1.0f / g_cc[b];
    float raws[4];
    raws[0] = g_Sh [b * CH + t];
    raws[1] = g_Xh [b * CH + t];
    raws[2] = g_Shp[b * CH + t] * inv_cc;
    raws[3] = g_Xhp[b * CH + t];
    #pragma unroll
    for (int seg = 0; seg < 4; seg++) {
        int idx = seg * CH + t;
        zs[idx] = (raws[seg] - mu[idx]) * rsqrtf(var[idx] + 1e-5f) * gamma[idx] + beta[idx];
    }
    __syncthreads();
    float acc = b1[t];
    for (int k = 0; k < 4 * CH; k++) acc += zs[k] * W1[(size_t)k * CH + t];
    y1s[t] = fmaxf(acc, 0.f);
    __syncthreads();
    if (t < CCOUT) {
        float a = b2[t];
        for (int j = 0; j < CH; j++) a += y1s[j] * W2[j * CCOUT + t];
        lg[t] = a;
    }
    __syncthreads();
    if (t == 0) {
        float mx = lg[0];
        for (int c = 1; c < CCOUT; c++) mx = fmaxf(mx, lg[c]);
        float e[CCOUT]; float sum = 0.f;
        for (int c = 0; c < CCOUT; c++) { e[c] = expf(lg[c] - mx); sum += e[c]; }
        for (int c = 0; c < CCOUT; c++) out[b * CCOUT + c] = e[c] / sum;
    }
}

// ---------------- host ----------------
extern "C" void kernel_launch(void* const* d_in, const int* in_sizes, int n_in,
                              void* d_out, int out_size) {
    const float* x     = (const float*)d_in[0];
    const int*   ei    = (const int*)  d_in[1];
    const float* w     = (const float*)d_in[2];
    const int*   batch = (const int*)  d_in[3];
    const int*   cn    = (const int*)  d_in[4];
    const int*   cc    = (const int*)  d_in[5];
    const int*   cb    = (const int*)  d_in[6];
    const float* W_in  = (const float*)d_in[7];
    const float* b_in  = (const float*)d_in[8];
    const float* W_blk = (const float*)d_in[9];
    const float* b_blk = (const float*)d_in[10];
    const float* gam   = (const float*)d_in[11];
    const float* bet   = (const float*)d_in[12];
    const float* mu    = (const float*)d_in[13];
    const float* var   = (const float*)d_in[14];
    const float* W1    = (const float*)d_in[15];
    const float* b1    = (const float*)d_in[16];
    const float* W2    = (const float*)d_in[17];
    const float* b2    = (const float*)d_in[18];
    float* out = (float*)d_out;

    int E  = in_sizes[2];
    int N  = in_sizes[3];
    int M  = in_sizes[4];
    int KC = in_sizes[6];
    const int* src = ei;
    const int* dst = ei + E;

    float *p_Sh, *p_Xh, *p_Shp, *p_Xhp, *p_dinvp, *p_deg;
    __half *p_xwh, *p_hh, *p_xph, *p_xwsh, *p_hph;
    int *p_cntE, *p_cntC, *p_cntN, *p_offE, *p_offC, *p_offN, *p_curE, *p_curC, *p_curN;
    cudaGetSymbolAddress((void**)&p_xwh,  g_xwh);
    cudaGetSymbolAddress((void**)&p_hh,   g_hh);
    cudaGetSymbolAddress((void**)&p_xph,  g_xph);
    cudaGetSymbolAddress((void**)&p_xwsh, g_xwsh);
    cudaGetSymbolAddress((void**)&p_hph,  g_hph);
    cudaGetSymbolAddress((void**)&p_Sh,   g_Sh);
    cudaGetSymbolAddress((void**)&p_Xh,   g_Xh);
    cudaGetSymbolAddress((void**)&p_Shp,  g_Shp);
    cudaGetSymbolAddress((void**)&p_Xhp,  g_Xhp);
    cudaGetSymbolAddress((void**)&p_dinvp, g_dinvp);
    cudaGetSymbolAddress((void**)&p_deg,  g_deg);
    cudaGetSymbolAddress((void**)&p_cntE, g_cntE);
    cudaGetSymbolAddress((void**)&p_cntC, g_cntC);
    cudaGetSymbolAddress((void**)&p_cntN, g_cntN);
    cudaGetSymbolAddress((void**)&p_offE, g_offE);
    cudaGetSymbolAddress((void**)&p_offC, g_offC);
    cudaGetSymbolAddress((void**)&p_offN, g_offN);
    cudaGetSymbolAddress((void**)&p_curE, g_curE);
    cudaGetSymbolAddress((void**)&p_curC, g_curC);
    cudaGetSymbolAddress((void**)&p_curN, g_curN);

    const int T = 256;
    int warpsN  = (int)(((long)N * 32 + T - 1) / T);
    int warpsKC = (int)(((long)KC * 32 + T - 1) / T);
    int bE = (N + SCAN_BS - 1) / SCAN_BS;
    int bC = (KC + SCAN_BS - 1) / SCAN_BS;
    int bN = (N + SCAN_BS - 1) / SCAN_BS;

    // ---- fork ----
    cudaEventRecord(hevStart, 0);

    // ===== s1: gemm1 (fp16 output), then aprime(ones) chain =====
    cudaStreamWaitEvent(hs1, hevStart, 0);
    gemm_tf32<<<(N + 127) / 128, 256, 0, hs1>>>(x, nullptr, W_in, nullptr, p_xwh, N, CH, nullptr);
    cudaEventRecord(hevGemm1, hs1);

    // ===== s2: C/N-side CSR build + pooling zeroing + ccounts =====
    cudaStreamWaitEvent(hs2, hevStart, 0);
    cudaMemsetAsync(p_cntC, 0, (size_t)KC * 4, hs2);
    cudaMemsetAsync(p_cntN, 0, (size_t)N * 4, hs2);
    cudaMemsetAsync(p_Sh,   0, (size_t)CB * CH * 4, hs2);
    cudaMemsetAsync(p_Xh,   0, (size_t)CB * CH * 4, hs2);
    cudaMemsetAsync(p_Shp,  0, (size_t)CB * CH * 4, hs2);
    cudaMemsetAsync(p_Xhp,  0, (size_t)CB * CH * 4, hs2);
    cudaEventRecord(hevZeroP, hs2);
    k_ccounts_bs<<<1, CB, 0, hs2>>>(cb, KC);
    k_histM<<<(M + T - 1) / T, T, 0, hs2>>>(cc, cn, M);
    k_scanA1<<<bC, 256, 0, hs2>>>(p_cntC, KC, 64);
    k_scanB1<<<1, 32, 0, hs2>>>(bC, 64, p_offC + KC);
    k_scanC1<<<bC, 256, 0, hs2>>>(p_cntC, p_offC, p_curC, KC, 64);
    k_scanA1<<<bN, 256, 0, hs2>>>(p_cntN, N, 128);
    k_scanB1<<<1, 32, 0, hs2>>>(bN, 128, p_offN + N);
    k_scanC1<<<bN, 256, 0, hs2>>>(p_cntN, p_offN, p_curN, N, 128);
    k_fillCN<<<(M + T - 1) / T, T, 0, hs2>>>(cn, cc, M);
    cudaEventRecord(hevFillCN, hs2);

    // ===== s0: E-side CSR build =====
    cudaMemsetAsync(p_cntE, 0, (size_t)N * 4, 0);
    cudaMemsetAsync(p_deg,  0, (size_t)N * 4, 0);
    k_histE<<<(E + T - 1) / T, T>>>(dst, E);
    k_scanA1<<<bE, 256>>>(p_cntE, N, 0);
    k_scanB1<<<1, 32>>>(bE, 0, p_offE + N);
    k_scanC1<<<bE, 256>>>(p_cntE, p_offE, p_curE, N, 0);
    k_fillE<<<(E + T - 1) / T, T>>>(src, dst, w, E);
    cudaEventRecord(hevFillE, 0);
    k_dinv<<<(N + T - 1) / T, T>>>(N);

    // s1: aprime(ones) chain (needs CSR-E + cntN/CSR-C)
    cudaStreamWaitEvent(hs1, hevFillE, 0);
    cudaStreamWaitEvent(hs1, hevFillCN, 0);
    k_ye1g   <<<(N + T - 1) / T, T, 0, hs1>>>(N);
    k_dinvp_g<<<(KC + T - 1) / T, T, 0, hs1>>>(KC);
    cudaEventRecord(hevDinvp, hs1);

    // s0: GCN pass 1 (needs xwh + CSR-E + dinv)
    cudaStreamWaitEvent(0, hevGemm1, 0);
    gather_gcn1<<<warpsN, T>>>(b_in, N);
    cudaEventRecord(hevH, 0);

    // s2: node pooling (after zeroing + ccounts on s2; needs hh)
    cudaStreamWaitEvent(hs2, hevH, 0);
    pool_sorted_h<<<(N + 63) / 64, CH, 0, hs2>>>(p_hh, batch, p_Sh, p_Xh, N, 64);
    cudaEventRecord(hevSide, hs2);

    // s0: cover pooling (fp16), gemm2 (fp16 A/out), aprime(xws) chain, hp (fp16), cluster pooling
    cudaStreamWaitEvent(0, hevFillCN, 0);
    gather_xp<<<warpsKC, T>>>(KC);
    cudaStreamWaitEvent(0, hevDinvp, 0);
    gemm_tf32<<<(KC + 127) / 128, 256>>>(nullptr, p_xph, W_blk, nullptr, p_xwsh, KC, 2 * CH, p_dinvp);
    gather_zn<<<warpsN, T>>>(N);
    gather_ye<<<warpsN, T>>>(N);
    gather_hp<<<warpsKC, T>>>(b_blk, KC);
    cudaStreamWaitEvent(0, hevZeroP, 0);
    pool_sorted_h<<<(KC + 63) / 64, CH>>>(p_hph, cb, p_Shp, p_Xhp, KC, 64);

    // ---- join + final ----
    cudaStreamWaitEvent(0, hevSide, 0);
    k_mlp<<<CB, CH>>>(gam, bet, mu, var, W1, b1, W2, b2, out);
}